// round 2
// baseline (speedup 1.0000x reference)
#include <cuda_runtime.h>
#include <math.h>

// Problem constants
#define BB 2
#define SS 2048
#define HH 2048
#define NHEAD 16
#define HDIM 128
#define H3 6144           // 3*H
#define VP 320
#define MALL 4096         // B*S

// -------- scratch (device globals; no allocation allowed) --------
__device__ float g_qkv[BB * SS * H3];   // 100.7 MB
__device__ float g_vc [BB * SS * VP];   // 5.2 MB
__device__ float g_vr [BB * SS * HH];   // 33.5 MB
__device__ float g_att[BB * SS * HH];   // 33.5 MB

// ============================================================================
// SGEMM: C[m][n] = sum_k A[m*lda + k] * Bw[n*K + k] + bias[n]
// M is always a multiple of 128 (4096). N may not be (320) -> guarded.
// K is a multiple of 8 (2048 or 320).
// 128x128 block tile, BK=8, 256 threads, 8x8 micro-tile.
// ============================================================================
__global__ __launch_bounds__(256) void sgemm_bias_kernel(
    const float* __restrict__ A, int lda,
    const float* __restrict__ Bw,
    const float* __restrict__ bias,
    float* __restrict__ C, int ldc,
    int N, int K)
{
    __shared__ float As[8][132];   // padded: store conflicts removed
    __shared__ float Bs[8][132];

    const int t  = threadIdx.x;
    const int tx = t & 15;
    const int ty = t >> 4;
    const int m0 = blockIdx.y * 128;
    const int n0 = blockIdx.x * 128;

    const int arow = t >> 1;            // 0..127
    const int acol = (t & 1) * 4;       // 0 or 4

    const float* Aload = A + (m0 + arow) * lda + acol;
    const int    brow  = n0 + arow;
    const float* Bload = Bw + brow * K + acol;
    const bool   bvalid = (brow < N);

    float acc[8][8];
#pragma unroll
    for (int i = 0; i < 8; i++)
#pragma unroll
        for (int j = 0; j < 8; j++) acc[i][j] = 0.0f;

    for (int kk = 0; kk < K; kk += 8) {
        float4 a = *(const float4*)(Aload + kk);
        float4 b = bvalid ? *(const float4*)(Bload + kk)
                          : make_float4(0.f, 0.f, 0.f, 0.f);
        As[acol + 0][arow] = a.x;
        As[acol + 1][arow] = a.y;
        As[acol + 2][arow] = a.z;
        As[acol + 3][arow] = a.w;
        Bs[acol + 0][arow] = b.x;
        Bs[acol + 1][arow] = b.y;
        Bs[acol + 2][arow] = b.z;
        Bs[acol + 3][arow] = b.w;
        __syncthreads();

#pragma unroll
        for (int k = 0; k < 8; k++) {
            float4 a0 = *(const float4*)&As[k][ty * 8];
            float4 a1 = *(const float4*)&As[k][ty * 8 + 4];
            float4 b0 = *(const float4*)&Bs[k][tx * 8];
            float4 b1 = *(const float4*)&Bs[k][tx * 8 + 4];
            float ra[8] = {a0.x, a0.y, a0.z, a0.w, a1.x, a1.y, a1.z, a1.w};
            float rb[8] = {b0.x, b0.y, b0.z, b0.w, b1.x, b1.y, b1.z, b1.w};
#pragma unroll
            for (int i = 0; i < 8; i++)
#pragma unroll
                for (int j = 0; j < 8; j++)
                    acc[i][j] += ra[i] * rb[j];
        }
        __syncthreads();
    }

#pragma unroll
    for (int i = 0; i < 8; i++) {
        int m = m0 + ty * 8 + i;
#pragma unroll
        for (int j = 0; j < 8; j++) {
            int n = n0 + tx * 8 + j;
            if (n < N) C[m * ldc + n] = acc[i][j] + bias[n];
        }
    }
}

// ============================================================================
// RoPE in place on q and k slices of g_qkv.
// rot dim = 32 per head: out[d]    = x[d]*cos - x[d+16]*sin   (d<16)
//                        out[d+16] = x[d+16]*cos + x[d]*sin
// angle(s, j) = s * 10000^(-2j/32), j = d mod 16.
// ============================================================================
__global__ void rope_kernel()
{
    int idx = blockIdx.x * blockDim.x + threadIdx.x;  // B*S*NH*16 items
    if (idx >= BB * SS * NHEAD * 16) return;
    int j = idx & 15;
    int h = (idx >> 4) & 15;
    int s = (idx >> 8) & 2047;
    int b = idx >> 19;

    // inv_freq = exp(-(2j/32) * ln(10000))
    float inv = __expf(-(float)(2 * j) * (9.210340371976184f / 32.0f));
    float ang = (float)s * inv;
    float sn, cs;
    sincosf(ang, &sn, &cs);

    int base = (b * SS + s) * H3 + h * HDIM;
    float q0 = g_qkv[base + j], q1 = g_qkv[base + j + 16];
    g_qkv[base + j]      = q0 * cs - q1 * sn;
    g_qkv[base + j + 16] = q1 * cs + q0 * sn;

    base += HH;  // k slice
    float k0 = g_qkv[base + j], k1 = g_qkv[base + j + 16];
    g_qkv[base + j]      = k0 * cs - k1 * sn;
    g_qkv[base + j + 16] = k1 * cs + k0 * sn;
}

// ============================================================================
// Flash attention (causal), fp32.
// Block = (q_tile of 64, head, batch); 256 threads (tx 0..15, ty 0..15).
// Each thread: 4 q-rows (ty*4+i), S-cols n = tx + 16*j, O cols tx*8..+7.
// smem: Qs/Ks/Vs 64x132 (padded), Ps 64x68.
// ============================================================================
#define QS_STRIDE 132
#define PS_STRIDE 68
#define FLASH_SMEM ((3 * 64 * QS_STRIDE + 64 * PS_STRIDE) * (int)sizeof(float))

__global__ __launch_bounds__(256, 1) void flash_kernel()
{
    extern __shared__ float sm[];
    float* Qs = sm;
    float* Ks = Qs + 64 * QS_STRIDE;
    float* Vs = Ks + 64 * QS_STRIDE;
    float* Ps = Vs + 64 * QS_STRIDE;

    const int qt = blockIdx.x;
    const int h  = blockIdx.y;
    const int b  = blockIdx.z;
    const int q0 = qt * 64;
    const int t  = threadIdx.x;
    const int tx = t & 15;
    const int ty = t >> 4;

    // Load Q tile (64 rows x 128 cols)
    for (int i = t; i < 64 * 32; i += 256) {
        int r  = i >> 5;
        int c4 = (i & 31) << 2;
        int gi = (b * SS + q0 + r) * H3 + h * HDIM + c4;
        *(float4*)&Qs[r * QS_STRIDE + c4] = *(const float4*)&g_qkv[gi];
    }

    float m_i[4], l_i[4], O[4][8];
#pragma unroll
    for (int i = 0; i < 4; i++) {
        m_i[i] = -1e30f;
        l_i[i] = 0.0f;
#pragma unroll
        for (int c = 0; c < 8; c++) O[i][c] = 0.0f;
    }
    const float scale = 0.08838834764831843f;  // 1/sqrt(128)

    for (int kt = 0; kt <= qt; kt++) {
        const int k0 = kt * 64;
        __syncthreads();  // previous tile fully consumed (also orders Q stores)

        // Load K and V tiles
        for (int i = t; i < 64 * 32; i += 256) {
            int r  = i >> 5;
            int c4 = (i & 31) << 2;
            int gk = (b * SS + k0 + r) * H3 + HH + h * HDIM + c4;
            *(float4*)&Ks[r * QS_STRIDE + c4] = *(const float4*)&g_qkv[gk];
            int gv = (b * SS + k0 + r) * HH + h * HDIM + c4;
            *(float4*)&Vs[r * QS_STRIDE + c4] = *(const float4*)&g_vr[gv];
        }
        __syncthreads();

        // S = Q K^T (4x4 fragment per thread)
        float acc[4][4];
#pragma unroll
        for (int i = 0; i < 4; i++)
#pragma unroll
            for (int j = 0; j < 4; j++) acc[i][j] = 0.0f;

#pragma unroll 4
        for (int k = 0; k < 128; k += 4) {
            float4 qv[4], kv[4];
#pragma unroll
            for (int i = 0; i < 4; i++)
                qv[i] = *(const float4*)&Qs[(ty * 4 + i) * QS_STRIDE + k];
#pragma unroll
            for (int j = 0; j < 4; j++)
                kv[j] = *(const float4*)&Ks[(tx + 16 * j) * QS_STRIDE + k];
#pragma unroll
            for (int i = 0; i < 4; i++)
#pragma unroll
                for (int j = 0; j < 4; j++) {
                    acc[i][j] += qv[i].x * kv[j].x;
                    acc[i][j] += qv[i].y * kv[j].y;
                    acc[i][j] += qv[i].z * kv[j].z;
                    acc[i][j] += qv[i].w * kv[j].w;
                }
        }

        // Online softmax (rows shared by the 16 tx-threads; lanes 0-15 / 16-31)
#pragma unroll
        for (int i = 0; i < 4; i++) {
            int qg = q0 + ty * 4 + i;
            float rmax = -1e30f;
#pragma unroll
            for (int j = 0; j < 4; j++) {
                float sv = acc[i][j] * scale;
                if (k0 + tx + 16 * j > qg) sv = -1e30f;  // causal (only diag tile)
                acc[i][j] = sv;
                rmax = fmaxf(rmax, sv);
            }
#pragma unroll
            for (int off = 8; off >= 1; off >>= 1)
                rmax = fmaxf(rmax, __shfl_xor_sync(0xffffffffu, rmax, off));
            float mnew = fmaxf(m_i[i], rmax);
            float corr = __expf(m_i[i] - mnew);
            float rsum = 0.0f;
#pragma unroll
            for (int j = 0; j < 4; j++) {
                float p = __expf(acc[i][j] - mnew);
                Ps[(ty * 4 + i) * PS_STRIDE + tx + 16 * j] = p;
                rsum += p;
            }
#pragma unroll
            for (int off = 8; off >= 1; off >>= 1)
                rsum += __shfl_xor_sync(0xffffffffu, rsum, off);
            l_i[i] = l_i[i] * corr + rsum;
            m_i[i] = mnew;
#pragma unroll
            for (int c = 0; c < 8; c++) O[i][c] *= corr;
        }
        __syncthreads();  // Ps visible

        // O += P V
#pragma unroll 8
        for (int n = 0; n < 64; n++) {
            float4 v0 = *(const float4*)&Vs[n * QS_STRIDE + tx * 8];
            float4 v1 = *(const float4*)&Vs[n * QS_STRIDE + tx * 8 + 4];
#pragma unroll
            for (int i = 0; i < 4; i++) {
                float p = Ps[(ty * 4 + i) * PS_STRIDE + n];
                O[i][0] += p * v0.x;  O[i][1] += p * v0.y;
                O[i][2] += p * v0.z;  O[i][3] += p * v0.w;
                O[i][4] += p * v1.x;  O[i][5] += p * v1.y;
                O[i][6] += p * v1.z;  O[i][7] += p * v1.w;
            }
        }
    }

    // Epilogue -> g_att in [B, S, H] layout (direct input to Wd GEMM)
#pragma unroll
    for (int i = 0; i < 4; i++) {
        float inv = 1.0f / l_i[i];
        int qg = q0 + ty * 4 + i;
        int o  = (b * SS + qg) * HH + h * HDIM + tx * 8;
        float4 r0 = make_float4(O[i][0] * inv, O[i][1] * inv,
                                O[i][2] * inv, O[i][3] * inv);
        float4 r1 = make_float4(O[i][4] * inv, O[i][5] * inv,
                                O[i][6] * inv, O[i][7] * inv);
        *(float4*)&g_att[o]     = r0;
        *(float4*)&g_att[o + 4] = r1;
    }
}

// ============================================================================
// Launch: QKV GEMM -> RoPE -> Vc GEMM -> Vr GEMM -> flash attn -> Wd GEMM
// ============================================================================
extern "C" void kernel_launch(void* const* d_in, const int* in_sizes, int n_in,
                              void* d_out, int out_size)
{
    const float* x    = (const float*)d_in[0];
    const float* Wqkv = (const float*)d_in[1];
    const float* bqkv = (const float*)d_in[2];
    const float* Wc   = (const float*)d_in[3];
    const float* bc   = (const float*)d_in[4];
    const float* Wr   = (const float*)d_in[5];
    const float* br   = (const float*)d_in[6];
    const float* Wd   = (const float*)d_in[7];
    const float* bd   = (const float*)d_in[8];
    float* out = (float*)d_out;

    float *qkv, *vc, *vr, *att;
    cudaGetSymbolAddress((void**)&qkv, g_qkv);
    cudaGetSymbolAddress((void**)&vc,  g_vc);
    cudaGetSymbolAddress((void**)&vr,  g_vr);
    cudaGetSymbolAddress((void**)&att, g_att);

    cudaFuncSetAttribute(flash_kernel,
                         cudaFuncAttributeMaxDynamicSharedMemorySize, FLASH_SMEM);

    dim3 thr(256);

    // 1. qkv = x @ Wqkv^T + bqkv   (M=4096, N=6144, K=2048)
    sgemm_bias_kernel<<<dim3(H3 / 128, MALL / 128), thr>>>(
        x, HH, Wqkv, bqkv, qkv, H3, H3, HH);

    // 2. RoPE on q, k (in place)
    rope_kernel<<<(BB * SS * NHEAD * 16) / 256, 256>>>();

    // 3. vc = v_slice @ Wc^T + bc  (M=4096, N=320, K=2048), A = qkv[:, 2H:3H]
    sgemm_bias_kernel<<<dim3((VP + 127) / 128, MALL / 128), thr>>>(
        qkv + 2 * HH, H3, Wc, bc, vc, VP, VP, HH);

    // 4. vr = vc @ Wr^T + br       (M=4096, N=2048, K=320)
    sgemm_bias_kernel<<<dim3(HH / 128, MALL / 128), thr>>>(
        vc, VP, Wr, br, vr, HH, HH, VP);

    // 5. causal flash attention    (grid: 32 q-tiles x 16 heads x 2 batch)
    flash_kernel<<<dim3(SS / 64, NHEAD, BB), thr, FLASH_SMEM>>>();

    // 6. out = att @ Wd^T + bd     (M=4096, N=2048, K=2048)
    sgemm_bias_kernel<<<dim3(HH / 128, MALL / 128), thr>>>(
        att, HH, Wd, bd, out, HH, HH, HH);
}

// round 4
// speedup vs baseline: 1.6430x; 1.6430x over previous
#include <cuda_runtime.h>
#include <cuda_bf16.h>
#include <mma.h>
#include <math.h>
#include <stdint.h>

using namespace nvcuda;

// Problem constants
#define BB 2
#define SS 2048
#define HH 2048
#define NHEAD 16
#define HDIM 128
#define H3 6144           // 3*H
#define VP 320
#define MALL 4096         // B*S

// -------- fp32 scratch --------
__device__ float g_qkv[BB * SS * H3];
__device__ float g_vc [BB * SS * VP];
__device__ float g_vr [BB * SS * HH];
__device__ float g_att[BB * SS * HH];

// -------- bf16 hi/lo scratch --------
__device__ __nv_bfloat16 g_xh [MALL * HH],  g_xl [MALL * HH];
__device__ __nv_bfloat16 g_wqh[H3 * HH],    g_wql[H3 * HH];
__device__ __nv_bfloat16 g_vh [MALL * HH],  g_vl [MALL * HH];
__device__ __nv_bfloat16 g_wch[VP * HH],    g_wcl[VP * HH];
__device__ __nv_bfloat16 g_vch[MALL * VP],  g_vcl[MALL * VP];
__device__ __nv_bfloat16 g_wrh[HH * VP],    g_wrl[HH * VP];
__device__ __nv_bfloat16 g_ath[MALL * HH],  g_atl[MALL * HH];
__device__ __nv_bfloat16 g_wdh[HH * HH],    g_wdl[HH * HH];

// ============================================================================
// cp.async helpers (base PTX, sm_80+; no 'a'-suffix features)
// ============================================================================
__device__ __forceinline__ uint32_t smem_u32(const void* p) {
    uint32_t a;
    asm("{ .reg .u64 t; cvta.to.shared.u64 t, %1; cvt.u32.u64 %0, t; }"
        : "=r"(a) : "l"(p));
    return a;
}
__device__ __forceinline__ void cp16(uint32_t s, const void* g, uint32_t nbytes) {
    // nbytes = 16 (copy) or 0 (zero-fill)
    asm volatile("cp.async.cg.shared.global [%0], [%1], 16, %2;"
                 :: "r"(s), "l"(g), "r"(nbytes) : "memory");
}
__device__ __forceinline__ void cp_commit() {
    asm volatile("cp.async.commit_group;" ::: "memory");
}
template <int N>
__device__ __forceinline__ void cp_wait() {
    asm volatile("cp.async.wait_group %0;" :: "n"(N) : "memory");
}

// ============================================================================
// fp32 -> bf16 (hi, lo) split conversion
// ============================================================================
__global__ void split_kernel(const float* __restrict__ src,
                             __nv_bfloat16* __restrict__ hi,
                             __nv_bfloat16* __restrict__ lo, int n)
{
    int i = (blockIdx.x * blockDim.x + threadIdx.x) * 4;
    if (i >= n) return;
    float4 v = *(const float4*)(src + i);
    __nv_bfloat16 h0 = __float2bfloat16(v.x);
    __nv_bfloat16 h1 = __float2bfloat16(v.y);
    __nv_bfloat16 h2 = __float2bfloat16(v.z);
    __nv_bfloat16 h3 = __float2bfloat16(v.w);
    __nv_bfloat16 l0 = __float2bfloat16(v.x - __bfloat162float(h0));
    __nv_bfloat16 l1 = __float2bfloat16(v.y - __bfloat162float(h1));
    __nv_bfloat16 l2 = __float2bfloat16(v.z - __bfloat162float(h2));
    __nv_bfloat16 l3 = __float2bfloat16(v.w - __bfloat162float(h3));
    *(__nv_bfloat162*)(hi + i)     = __nv_bfloat162(h0, h1);
    *(__nv_bfloat162*)(hi + i + 2) = __nv_bfloat162(h2, h3);
    *(__nv_bfloat162*)(lo + i)     = __nv_bfloat162(l0, l1);
    *(__nv_bfloat162*)(lo + i + 2) = __nv_bfloat162(l2, l3);
}

// v slice of g_qkv (strided) -> contiguous bf16 hi/lo [MALL x HH]
__global__ void split_v_kernel()
{
    int i = (blockIdx.x * blockDim.x + threadIdx.x) * 4;
    if (i >= MALL * HH) return;
    int r = i / HH, c = i % HH;
    float4 v = *(const float4*)(g_qkv + (size_t)r * H3 + 2 * HH + c);
    __nv_bfloat16 h0 = __float2bfloat16(v.x);
    __nv_bfloat16 h1 = __float2bfloat16(v.y);
    __nv_bfloat16 h2 = __float2bfloat16(v.z);
    __nv_bfloat16 h3 = __float2bfloat16(v.w);
    __nv_bfloat16 l0 = __float2bfloat16(v.x - __bfloat162float(h0));
    __nv_bfloat16 l1 = __float2bfloat16(v.y - __bfloat162float(h1));
    __nv_bfloat16 l2 = __float2bfloat16(v.z - __bfloat162float(h2));
    __nv_bfloat16 l3 = __float2bfloat16(v.w - __bfloat162float(h3));
    *(__nv_bfloat162*)(g_vh + i)     = __nv_bfloat162(h0, h1);
    *(__nv_bfloat162*)(g_vh + i + 2) = __nv_bfloat162(h2, h3);
    *(__nv_bfloat162*)(g_vl + i)     = __nv_bfloat162(l0, l1);
    *(__nv_bfloat162*)(g_vl + i + 2) = __nv_bfloat162(l2, l3);
}

// ============================================================================
// WMMA split-bf16 GEMM: C[m][n] = sum_k A[m][k]*B[n][k] + bias[n]
// A = Ah+Al, B = Bh+Bl. 128x128 CTA tile, K-chunk 32, cp.async double buffer.
// 8 warps: warp (wr, wc) in 2x4 grid owns 64x32; 4x2 wmma 16x16x16 frags.
// ============================================================================
#define PAD      40                       // smem row stride in bf16 elems (80 B)
#define TILE_SM  (128 * PAD * 2)          // 10240 B per tile
#define STAGE_SM (4 * TILE_SM)            // Ah, Al, Bh, Bl : 40960 B
#define GEMM_SMEM (2 * STAGE_SM)          // 81920 B

__global__ __launch_bounds__(256, 1) void gemm_wmma_kernel(
    const __nv_bfloat16* __restrict__ Ah, const __nv_bfloat16* __restrict__ Al,
    const __nv_bfloat16* __restrict__ Bh, const __nv_bfloat16* __restrict__ Bl,
    const float* __restrict__ bias, float* __restrict__ C,
    int ldc, int N, int K)
{
    extern __shared__ char smem[];
    const uint32_t sbase = smem_u32(smem);
    const int t    = threadIdx.x;
    const int w    = t >> 5;
    const int lane = t & 31;
    const int wr   = w >> 2;     // 0..1 (M)
    const int wc   = w & 3;      // 0..3 (N)
    const int m0   = blockIdx.y * 128;
    const int n0   = blockIdx.x * 128;

    wmma::fragment<wmma::accumulator, 16, 16, 16, float> acc[4][2];
#pragma unroll
    for (int i = 0; i < 4; i++)
#pragma unroll
        for (int j = 0; j < 2; j++) wmma::fill_fragment(acc[i][j], 0.0f);

    const int nchunks = K / 32;

    // ---- stage loader: 4 tiles x 512 16B-chunks, 8 cp.async per thread ----
    auto load_stage = [&](int chunk, int stage) {
        const int kk = chunk * 32;
        const uint32_t sst = sbase + stage * STAGE_SM;
#pragma unroll
        for (int half = 0; half < 2; half++) {
            const int i = t + half * 256;       // 0..511
            const int r = i >> 2;               // 0..127
            const int c = (i & 3) * 8;          // 0,8,16,24
            const uint32_t soff = r * (PAD * 2) + c * 2;
            // A tiles (always valid)
            const size_t ga = (size_t)(m0 + r) * K + kk + c;
            cp16(sst + soff,               Ah + ga, 16);
            cp16(sst + TILE_SM + soff,     Al + ga, 16);
            // B tiles (guard rows >= N with zero-fill)
            const int brow = n0 + r;
            const uint32_t vb = (brow < N) ? 16u : 0u;
            const size_t gb = (size_t)(brow < N ? brow : 0) * K + kk + c;
            cp16(sst + 2 * TILE_SM + soff, Bh + gb, vb);
            cp16(sst + 3 * TILE_SM + soff, Bl + gb, vb);
        }
        cp_commit();
    };

    load_stage(0, 0);

    for (int chunk = 0; chunk < nchunks; chunk++) {
        const int stage = chunk & 1;
        if (chunk + 1 < nchunks) {
            load_stage(chunk + 1, stage ^ 1);
            cp_wait<1>();
        } else {
            cp_wait<0>();
        }
        __syncthreads();

        const __nv_bfloat16* sAh = (const __nv_bfloat16*)(smem + stage * STAGE_SM);
        const __nv_bfloat16* sAl = (const __nv_bfloat16*)(smem + stage * STAGE_SM + TILE_SM);
        const __nv_bfloat16* sBh = (const __nv_bfloat16*)(smem + stage * STAGE_SM + 2 * TILE_SM);
        const __nv_bfloat16* sBl = (const __nv_bfloat16*)(smem + stage * STAGE_SM + 3 * TILE_SM);

#pragma unroll
        for (int ks = 0; ks < 2; ks++) {
            wmma::fragment<wmma::matrix_a, 16, 16, 16, __nv_bfloat16, wmma::row_major> ah[4], al[4];
            wmma::fragment<wmma::matrix_b, 16, 16, 16, __nv_bfloat16, wmma::col_major> bh[2], bl[2];
#pragma unroll
            for (int i = 0; i < 4; i++) {
                const int row = wr * 64 + i * 16;
                wmma::load_matrix_sync(ah[i], sAh + row * PAD + ks * 16, PAD);
                wmma::load_matrix_sync(al[i], sAl + row * PAD + ks * 16, PAD);
            }
#pragma unroll
            for (int j = 0; j < 2; j++) {
                const int col = wc * 32 + j * 16;
                wmma::load_matrix_sync(bh[j], sBh + col * PAD + ks * 16, PAD);
                wmma::load_matrix_sync(bl[j], sBl + col * PAD + ks * 16, PAD);
            }
#pragma unroll
            for (int i = 0; i < 4; i++)
#pragma unroll
                for (int j = 0; j < 2; j++) {
                    wmma::mma_sync(acc[i][j], ah[i], bh[j], acc[i][j]);
                    wmma::mma_sync(acc[i][j], ah[i], bl[j], acc[i][j]);
                    wmma::mma_sync(acc[i][j], al[i], bh[j], acc[i][j]);
                }
        }
        __syncthreads();
    }

    // ---- epilogue: frag -> per-warp smem -> bias add -> float4 stores ----
    float* epi = (float*)(smem) + w * 256;     // 16x16 per warp
#pragma unroll
    for (int i = 0; i < 4; i++)
#pragma unroll
        for (int j = 0; j < 2; j++) {
            const int gcol0 = n0 + wc * 32 + j * 16;
            if (gcol0 < N) {
                wmma::store_matrix_sync(epi, acc[i][j], 16, wmma::mem_row_major);
                __syncwarp();
                const int row  = lane >> 1;
                const int coff = (lane & 1) * 8;
                const int grow = m0 + wr * 64 + i * 16 + row;
                const int gcol = gcol0 + coff;
                float4 b0 = *(const float4*)(bias + gcol);
                float4 b1 = *(const float4*)(bias + gcol + 4);
                const float* e = epi + row * 16 + coff;
                float4 v0 = make_float4(e[0] + b0.x, e[1] + b0.y, e[2] + b0.z, e[3] + b0.w);
                float4 v1 = make_float4(e[4] + b1.x, e[5] + b1.y, e[6] + b1.z, e[7] + b1.w);
                float* cp = C + (size_t)grow * ldc + gcol;
                *(float4*)cp       = v0;
                *(float4*)(cp + 4) = v1;
                __syncwarp();
            }
        }
}

// ============================================================================
// RoPE in place on q and k slices of g_qkv (rot dim 32, half-split 16/16).
// ============================================================================
__global__ void rope_kernel()
{
    int idx = blockIdx.x * blockDim.x + threadIdx.x;
    if (idx >= BB * SS * NHEAD * 16) return;
    int j = idx & 15;
    int h = (idx >> 4) & 15;
    int s = (idx >> 8) & 2047;
    int b = idx >> 19;

    float inv = __expf(-(float)(2 * j) * (9.210340371976184f / 32.0f));
    float ang = (float)s * inv;
    float sn, cs;
    sincosf(ang, &sn, &cs);

    int base = (b * SS + s) * H3 + h * HDIM;
    float q0 = g_qkv[base + j], q1 = g_qkv[base + j + 16];
    g_qkv[base + j]      = q0 * cs - q1 * sn;
    g_qkv[base + j + 16] = q1 * cs + q0 * sn;

    base += HH;
    float k0 = g_qkv[base + j], k1 = g_qkv[base + j + 16];
    g_qkv[base + j]      = k0 * cs - k1 * sn;
    g_qkv[base + j + 16] = k1 * cs + k0 * sn;
}

// ============================================================================
// Flash attention (causal), fp32 (unchanged from R2 passing version)
// ============================================================================
#define QS_STRIDE 132
#define PS_STRIDE 68
#define FLASH_SMEM ((3 * 64 * QS_STRIDE + 64 * PS_STRIDE) * (int)sizeof(float))

__global__ __launch_bounds__(256, 1) void flash_kernel()
{
    extern __shared__ float sm[];
    float* Qs = sm;
    float* Ks = Qs + 64 * QS_STRIDE;
    float* Vs = Ks + 64 * QS_STRIDE;
    float* Ps = Vs + 64 * QS_STRIDE;

    const int qt = blockIdx.x;
    const int h  = blockIdx.y;
    const int b  = blockIdx.z;
    const int q0 = qt * 64;
    const int t  = threadIdx.x;
    const int tx = t & 15;
    const int ty = t >> 4;

    for (int i = t; i < 64 * 32; i += 256) {
        int r  = i >> 5;
        int c4 = (i & 31) << 2;
        int gi = (b * SS + q0 + r) * H3 + h * HDIM + c4;
        *(float4*)&Qs[r * QS_STRIDE + c4] = *(const float4*)&g_qkv[gi];
    }

    float m_i[4], l_i[4], O[4][8];
#pragma unroll
    for (int i = 0; i < 4; i++) {
        m_i[i] = -1e30f;
        l_i[i] = 0.0f;
#pragma unroll
        for (int c = 0; c < 8; c++) O[i][c] = 0.0f;
    }
    const float scale = 0.08838834764831843f;

    for (int kt = 0; kt <= qt; kt++) {
        const int k0 = kt * 64;
        __syncthreads();

        for (int i = t; i < 64 * 32; i += 256) {
            int r  = i >> 5;
            int c4 = (i & 31) << 2;
            int gk = (b * SS + k0 + r) * H3 + HH + h * HDIM + c4;
            *(float4*)&Ks[r * QS_STRIDE + c4] = *(const float4*)&g_qkv[gk];
            int gv = (b * SS + k0 + r) * HH + h * HDIM + c4;
            *(float4*)&Vs[r * QS_STRIDE + c4] = *(const float4*)&g_vr[gv];
        }
        __syncthreads();

        float acc[4][4];
#pragma unroll
        for (int i = 0; i < 4; i++)
#pragma unroll
            for (int j = 0; j < 4; j++) acc[i][j] = 0.0f;

#pragma unroll 4
        for (int k = 0; k < 128; k += 4) {
            float4 qv[4], kv[4];
#pragma unroll
            for (int i = 0; i < 4; i++)
                qv[i] = *(const float4*)&Qs[(ty * 4 + i) * QS_STRIDE + k];
#pragma unroll
            for (int j = 0; j < 4; j++)
                kv[j] = *(const float4*)&Ks[(tx + 16 * j) * QS_STRIDE + k];
#pragma unroll
            for (int i = 0; i < 4; i++)
#pragma unroll
                for (int j = 0; j < 4; j++) {
                    acc[i][j] += qv[i].x * kv[j].x;
                    acc[i][j] += qv[i].y * kv[j].y;
                    acc[i][j] += qv[i].z * kv[j].z;
                    acc[i][j] += qv[i].w * kv[j].w;
                }
        }

#pragma unroll
        for (int i = 0; i < 4; i++) {
            int qg = q0 + ty * 4 + i;
            float rmax = -1e30f;
#pragma unroll
            for (int j = 0; j < 4; j++) {
                float sv = acc[i][j] * scale;
                if (k0 + tx + 16 * j > qg) sv = -1e30f;
                acc[i][j] = sv;
                rmax = fmaxf(rmax, sv);
            }
#pragma unroll
            for (int off = 8; off >= 1; off >>= 1)
                rmax = fmaxf(rmax, __shfl_xor_sync(0xffffffffu, rmax, off));
            float mnew = fmaxf(m_i[i], rmax);
            float corr = __expf(m_i[i] - mnew);
            float rsum = 0.0f;
#pragma unroll
            for (int j = 0; j < 4; j++) {
                float p = __expf(acc[i][j] - mnew);
                Ps[(ty * 4 + i) * PS_STRIDE + tx + 16 * j] = p;
                rsum += p;
            }
#pragma unroll
            for (int off = 8; off >= 1; off >>= 1)
                rsum += __shfl_xor_sync(0xffffffffu, rsum, off);
            l_i[i] = l_i[i] * corr + rsum;
            m_i[i] = mnew;
#pragma unroll
            for (int c = 0; c < 8; c++) O[i][c] *= corr;
        }
        __syncthreads();

#pragma unroll 8
        for (int n = 0; n < 64; n++) {
            float4 v0 = *(const float4*)&Vs[n * QS_STRIDE + tx * 8];
            float4 v1 = *(const float4*)&Vs[n * QS_STRIDE + tx * 8 + 4];
#pragma unroll
            for (int i = 0; i < 4; i++) {
                float p = Ps[(ty * 4 + i) * PS_STRIDE + n];
                O[i][0] += p * v0.x;  O[i][1] += p * v0.y;
                O[i][2] += p * v0.z;  O[i][3] += p * v0.w;
                O[i][4] += p * v1.x;  O[i][5] += p * v1.y;
                O[i][6] += p * v1.z;  O[i][7] += p * v1.w;
            }
        }
    }

#pragma unroll
    for (int i = 0; i < 4; i++) {
        float inv = 1.0f / l_i[i];
        int qg = q0 + ty * 4 + i;
        int o  = (b * SS + qg) * HH + h * HDIM + tx * 8;
        float4 r0 = make_float4(O[i][0] * inv, O[i][1] * inv,
                                O[i][2] * inv, O[i][3] * inv);
        float4 r1 = make_float4(O[i][4] * inv, O[i][5] * inv,
                                O[i][6] * inv, O[i][7] * inv);
        *(float4*)&g_att[o]     = r0;
        *(float4*)&g_att[o + 4] = r1;
    }
}

// ============================================================================
// Launch
// ============================================================================
static inline void split_launch(const float* s, __nv_bfloat16* h, __nv_bfloat16* l, int n)
{
    split_kernel<<<(n / 4 + 255) / 256, 256>>>(s, h, l, n);
}

extern "C" void kernel_launch(void* const* d_in, const int* in_sizes, int n_in,
                              void* d_out, int out_size)
{
    const float* x    = (const float*)d_in[0];
    const float* Wqkv = (const float*)d_in[1];
    const float* bqkv = (const float*)d_in[2];
    const float* Wc   = (const float*)d_in[3];
    const float* bc   = (const float*)d_in[4];
    const float* Wr   = (const float*)d_in[5];
    const float* br   = (const float*)d_in[6];
    const float* Wd   = (const float*)d_in[7];
    const float* bd   = (const float*)d_in[8];
    float* out = (float*)d_out;

    float *qkv, *vc, *vr, *att;
    cudaGetSymbolAddress((void**)&qkv, g_qkv);
    cudaGetSymbolAddress((void**)&vc,  g_vc);
    cudaGetSymbolAddress((void**)&vr,  g_vr);
    cudaGetSymbolAddress((void**)&att, g_att);
    __nv_bfloat16 *xh, *xl, *wqh, *wql, *vh, *vl, *wch, *wcl,
                  *vch, *vcl, *wrh, *wrl, *ath, *atl, *wdh, *wdl;
    cudaGetSymbolAddress((void**)&xh,  g_xh);  cudaGetSymbolAddress((void**)&xl,  g_xl);
    cudaGetSymbolAddress((void**)&wqh, g_wqh); cudaGetSymbolAddress((void**)&wql, g_wql);
    cudaGetSymbolAddress((void**)&vh,  g_vh);  cudaGetSymbolAddress((void**)&vl,  g_vl);
    cudaGetSymbolAddress((void**)&wch, g_wch); cudaGetSymbolAddress((void**)&wcl, g_wcl);
    cudaGetSymbolAddress((void**)&vch, g_vch); cudaGetSymbolAddress((void**)&vcl, g_vcl);
    cudaGetSymbolAddress((void**)&wrh, g_wrh); cudaGetSymbolAddress((void**)&wrl, g_wrl);
    cudaGetSymbolAddress((void**)&ath, g_ath); cudaGetSymbolAddress((void**)&atl, g_atl);
    cudaGetSymbolAddress((void**)&wdh, g_wdh); cudaGetSymbolAddress((void**)&wdl, g_wdl);

    cudaFuncSetAttribute(gemm_wmma_kernel,
                         cudaFuncAttributeMaxDynamicSharedMemorySize, GEMM_SMEM);
    cudaFuncSetAttribute(flash_kernel,
                         cudaFuncAttributeMaxDynamicSharedMemorySize, FLASH_SMEM);

    // 1. qkv = x @ Wqkv^T + bqkv   (M=4096, N=6144, K=2048)
    split_launch(x, xh, xl, MALL * HH);
    split_launch(Wqkv, wqh, wql, H3 * HH);
    gemm_wmma_kernel<<<dim3(H3 / 128, MALL / 128), 256, GEMM_SMEM>>>(
        xh, xl, wqh, wql, bqkv, qkv, H3, H3, HH);

    // 2. RoPE
    rope_kernel<<<(BB * SS * NHEAD * 16) / 256, 256>>>();

    // 3. vc = v @ Wc^T + bc        (M=4096, N=320, K=2048)
    split_v_kernel<<<(MALL * HH / 4 + 255) / 256, 256>>>();
    split_launch(Wc, wch, wcl, VP * HH);
    gemm_wmma_kernel<<<dim3((VP + 127) / 128, MALL / 128), 256, GEMM_SMEM>>>(
        vh, vl, wch, wcl, bc, vc, VP, VP, HH);

    // 4. vr = vc @ Wr^T + br       (M=4096, N=2048, K=320)
    split_launch(vc, vch, vcl, MALL * VP);
    split_launch(Wr, wrh, wrl, HH * VP);
    gemm_wmma_kernel<<<dim3(HH / 128, MALL / 128), 256, GEMM_SMEM>>>(
        vch, vcl, wrh, wrl, br, vr, HH, HH, VP);

    // 5. flash attention (fp32)
    flash_kernel<<<dim3(SS / 64, NHEAD, BB), 256, FLASH_SMEM>>>();

    // 6. out = att @ Wd^T + bd     (M=4096, N=2048, K=2048)
    split_launch(att, ath, atl, MALL * HH);
    split_launch(Wd, wdh, wdl, HH * HH);
    gemm_wmma_kernel<<<dim3(HH / 128, MALL / 128), 256, GEMM_SMEM>>>(
        ath, atl, wdh, wdl, bd, out, HH, HH, HH);
}

// round 5
// speedup vs baseline: 1.9701x; 1.1991x over previous
#include <cuda_runtime.h>
#include <cuda_bf16.h>
#include <mma.h>
#include <math.h>
#include <stdint.h>

using namespace nvcuda;

// Problem constants
#define BB 2
#define SS 2048
#define HH 2048
#define NHEAD 16
#define HDIM 128
#define H3 6144
#define VP 320
#define MALL 4096

// -------- fp32 scratch --------
__device__ float g_qkv[BB * SS * H3];
__device__ float g_vc [BB * SS * VP];
__device__ float g_vr [BB * SS * HH];

// -------- bf16 hi/lo scratch --------
__device__ __nv_bfloat16 g_xh [MALL * HH],  g_xl [MALL * HH];
__device__ __nv_bfloat16 g_wqh[H3 * HH],    g_wql[H3 * HH];
__device__ __nv_bfloat16 g_vh [MALL * HH],  g_vl [MALL * HH];   // v slice (Vc input)
__device__ __nv_bfloat16 g_wch[VP * HH],    g_wcl[VP * HH];
__device__ __nv_bfloat16 g_vch[MALL * VP],  g_vcl[MALL * VP];
__device__ __nv_bfloat16 g_wrh[HH * VP],    g_wrl[HH * VP];
__device__ __nv_bfloat16 g_ath[MALL * HH],  g_atl[MALL * HH];
__device__ __nv_bfloat16 g_wdh[HH * HH],    g_wdl[HH * HH];
// flash operands (roped q/k, restored v)
__device__ __nv_bfloat16 g_qh [MALL * HH],  g_ql [MALL * HH];
__device__ __nv_bfloat16 g_kh [MALL * HH],  g_kl [MALL * HH];
__device__ __nv_bfloat16 g_vrh[MALL * HH],  g_vrl[MALL * HH];

// ============================================================================
// helpers
// ============================================================================
__device__ __forceinline__ uint32_t smem_u32(const void* p) {
    uint32_t a;
    asm("{ .reg .u64 t; cvta.to.shared.u64 t, %1; cvt.u32.u64 %0, t; }"
        : "=r"(a) : "l"(p));
    return a;
}
__device__ __forceinline__ void cp16(uint32_t s, const void* g, uint32_t nbytes) {
    asm volatile("cp.async.cg.shared.global [%0], [%1], 16, %2;"
                 :: "r"(s), "l"(g), "r"(nbytes) : "memory");
}
__device__ __forceinline__ void cp_commit() {
    asm volatile("cp.async.commit_group;" ::: "memory");
}
template <int N>
__device__ __forceinline__ void cp_wait() {
    asm volatile("cp.async.wait_group %0;" :: "n"(N) : "memory");
}
__device__ __forceinline__ void split1(float v, __nv_bfloat16& h, __nv_bfloat16& l) {
    h = __float2bfloat16(v);
    l = __float2bfloat16(v - __bfloat162float(h));
}

// ============================================================================
// fp32 -> bf16 (hi, lo) split
// ============================================================================
__global__ void split_kernel(const float* __restrict__ src,
                             __nv_bfloat16* __restrict__ hi,
                             __nv_bfloat16* __restrict__ lo, int n)
{
    int i = (blockIdx.x * blockDim.x + threadIdx.x) * 4;
    if (i >= n) return;
    float4 v = *(const float4*)(src + i);
    __nv_bfloat16 h0, h1, h2, h3, l0, l1, l2, l3;
    split1(v.x, h0, l0); split1(v.y, h1, l1);
    split1(v.z, h2, l2); split1(v.w, h3, l3);
    *(__nv_bfloat162*)(hi + i)     = __nv_bfloat162(h0, h1);
    *(__nv_bfloat162*)(hi + i + 2) = __nv_bfloat162(h2, h3);
    *(__nv_bfloat162*)(lo + i)     = __nv_bfloat162(l0, l1);
    *(__nv_bfloat162*)(lo + i + 2) = __nv_bfloat162(l2, l3);
}

// v slice of g_qkv (strided) -> contiguous bf16 hi/lo [MALL x HH]
__global__ void split_v_kernel()
{
    int i = (blockIdx.x * blockDim.x + threadIdx.x) * 4;
    if (i >= MALL * HH) return;
    int r = i / HH, c = i % HH;
    float4 v = *(const float4*)(g_qkv + (size_t)r * H3 + 2 * HH + c);
    __nv_bfloat16 h0, h1, h2, h3, l0, l1, l2, l3;
    split1(v.x, h0, l0); split1(v.y, h1, l1);
    split1(v.z, h2, l2); split1(v.w, h3, l3);
    *(__nv_bfloat162*)(g_vh + i)     = __nv_bfloat162(h0, h1);
    *(__nv_bfloat162*)(g_vh + i + 2) = __nv_bfloat162(h2, h3);
    *(__nv_bfloat162*)(g_vl + i)     = __nv_bfloat162(l0, l1);
    *(__nv_bfloat162*)(g_vl + i + 2) = __nv_bfloat162(l2, l3);
}

// ============================================================================
// fused RoPE + split for q, k: reads fp32 g_qkv, writes qh/ql/kh/kl [MALL x HH]
// one warp per (b, s, h); lane owns dims 4*lane .. 4*lane+3
// ============================================================================
__global__ void rope_split_kernel()
{
    const int gw   = blockIdx.x * 8 + (threadIdx.x >> 5);  // 0 .. B*S*NH-1
    const int lane = threadIdx.x & 31;
    const int h = gw & 15;
    const int s = (gw >> 4) & 2047;
    const int b = gw >> 15;

    const size_t qbase = (size_t)(b * SS + s) * H3 + h * HDIM;
    const int d0 = lane * 4;
    float4 q = *(const float4*)(g_qkv + qbase + d0);
    float4 k = *(const float4*)(g_qkv + qbase + HH + d0);

    // rope for dims < 32 (lanes 0..7); partner at lane ^ 2 (dims +-16)
    float4 qp, kp;
    qp.x = __shfl_xor_sync(0xffffffffu, q.x, 4);
    qp.y = __shfl_xor_sync(0xffffffffu, q.y, 4);
    qp.z = __shfl_xor_sync(0xffffffffu, q.z, 4);
    qp.w = __shfl_xor_sync(0xffffffffu, q.w, 4);
    kp.x = __shfl_xor_sync(0xffffffffu, k.x, 4);
    kp.y = __shfl_xor_sync(0xffffffffu, k.y, 4);
    kp.z = __shfl_xor_sync(0xffffffffu, k.z, 4);
    kp.w = __shfl_xor_sync(0xffffffffu, k.w, 4);

    if (lane < 8) {
        const float sgn = (lane < 4) ? -1.0f : 1.0f;   // first half: -x2*sin
        float qa[4] = {q.x, q.y, q.z, q.w};
        float pa[4] = {qp.x, qp.y, qp.z, qp.w};
        float ka[4] = {k.x, k.y, k.z, k.w};
        float kb[4] = {kp.x, kp.y, kp.z, kp.w};
#pragma unroll
        for (int i = 0; i < 4; i++) {
            int j = (lane & 3) * 4 + i;                 // freq index 0..15
            float inv = __expf(-(float)(2 * j) * (9.210340371976184f / 32.0f));
            float sn, cs;
            sincosf((float)s * inv, &sn, &cs);
            qa[i] = qa[i] * cs + sgn * pa[i] * sn;
            ka[i] = ka[i] * cs + sgn * kb[i] * sn;
        }
        q = make_float4(qa[0], qa[1], qa[2], qa[3]);
        k = make_float4(ka[0], ka[1], ka[2], ka[3]);
    }

    const size_t o = (size_t)(b * SS + s) * HH + h * HDIM + d0;
    __nv_bfloat16 h0, h1, h2, h3, l0, l1, l2, l3;
    split1(q.x, h0, l0); split1(q.y, h1, l1);
    split1(q.z, h2, l2); split1(q.w, h3, l3);
    *(__nv_bfloat162*)(g_qh + o)     = __nv_bfloat162(h0, h1);
    *(__nv_bfloat162*)(g_qh + o + 2) = __nv_bfloat162(h2, h3);
    *(__nv_bfloat162*)(g_ql + o)     = __nv_bfloat162(l0, l1);
    *(__nv_bfloat162*)(g_ql + o + 2) = __nv_bfloat162(l2, l3);
    split1(k.x, h0, l0); split1(k.y, h1, l1);
    split1(k.z, h2, l2); split1(k.w, h3, l3);
    *(__nv_bfloat162*)(g_kh + o)     = __nv_bfloat162(h0, h1);
    *(__nv_bfloat162*)(g_kh + o + 2) = __nv_bfloat162(h2, h3);
    *(__nv_bfloat162*)(g_kl + o)     = __nv_bfloat162(l0, l1);
    *(__nv_bfloat162*)(g_kl + o + 2) = __nv_bfloat162(l2, l3);
}

// ============================================================================
// WMMA split-bf16 GEMM (3-stage cp.async pipeline)
// ============================================================================
#define PAD      40
#define TILE_SM  (128 * PAD * 2)
#define STAGE_SM (4 * TILE_SM)
#define GEMM_SMEM (3 * STAGE_SM)

__global__ __launch_bounds__(256, 1) void gemm_wmma_kernel(
    const __nv_bfloat16* __restrict__ Ah, const __nv_bfloat16* __restrict__ Al,
    const __nv_bfloat16* __restrict__ Bh, const __nv_bfloat16* __restrict__ Bl,
    const float* __restrict__ bias, float* __restrict__ C,
    int ldc, int N, int K)
{
    extern __shared__ char smem[];
    const uint32_t sbase = smem_u32(smem);
    const int t    = threadIdx.x;
    const int w    = t >> 5;
    const int lane = t & 31;
    const int wr   = w >> 2;
    const int wc   = w & 3;
    const int m0   = blockIdx.y * 128;
    const int n0   = blockIdx.x * 128;

    wmma::fragment<wmma::accumulator, 16, 16, 16, float> acc[4][2];
#pragma unroll
    for (int i = 0; i < 4; i++)
#pragma unroll
        for (int j = 0; j < 2; j++) wmma::fill_fragment(acc[i][j], 0.0f);

    const int nchunks = K / 32;

    auto load_stage = [&](int chunk, int stage) {
        const int kk = chunk * 32;
        const uint32_t sst = sbase + stage * STAGE_SM;
#pragma unroll
        for (int half = 0; half < 2; half++) {
            const int i = t + half * 256;
            const int r = i >> 2;
            const int c = (i & 3) * 8;
            const uint32_t soff = r * (PAD * 2) + c * 2;
            const size_t ga = (size_t)(m0 + r) * K + kk + c;
            cp16(sst + soff,               Ah + ga, 16);
            cp16(sst + TILE_SM + soff,     Al + ga, 16);
            const int brow = n0 + r;
            const uint32_t vb = (brow < N) ? 16u : 0u;
            const size_t gb = (size_t)(brow < N ? brow : 0) * K + kk + c;
            cp16(sst + 2 * TILE_SM + soff, Bh + gb, vb);
            cp16(sst + 3 * TILE_SM + soff, Bl + gb, vb);
        }
        cp_commit();
    };

    load_stage(0, 0);
    if (nchunks > 1) load_stage(1, 1);

    for (int chunk = 0; chunk < nchunks; chunk++) {
        const int stage = chunk % 3;
        if (chunk + 2 < nchunks) { load_stage(chunk + 2, (chunk + 2) % 3); cp_wait<2>(); }
        else if (chunk + 1 < nchunks) cp_wait<1>();
        else cp_wait<0>();
        __syncthreads();

        const __nv_bfloat16* sAh = (const __nv_bfloat16*)(smem + stage * STAGE_SM);
        const __nv_bfloat16* sAl = (const __nv_bfloat16*)(smem + stage * STAGE_SM + TILE_SM);
        const __nv_bfloat16* sBh = (const __nv_bfloat16*)(smem + stage * STAGE_SM + 2 * TILE_SM);
        const __nv_bfloat16* sBl = (const __nv_bfloat16*)(smem + stage * STAGE_SM + 3 * TILE_SM);

#pragma unroll
        for (int ks = 0; ks < 2; ks++) {
            wmma::fragment<wmma::matrix_a, 16, 16, 16, __nv_bfloat16, wmma::row_major> ah[4], al[4];
            wmma::fragment<wmma::matrix_b, 16, 16, 16, __nv_bfloat16, wmma::col_major> bh[2], bl[2];
#pragma unroll
            for (int i = 0; i < 4; i++) {
                const int row = wr * 64 + i * 16;
                wmma::load_matrix_sync(ah[i], sAh + row * PAD + ks * 16, PAD);
                wmma::load_matrix_sync(al[i], sAl + row * PAD + ks * 16, PAD);
            }
#pragma unroll
            for (int j = 0; j < 2; j++) {
                const int col = wc * 32 + j * 16;
                wmma::load_matrix_sync(bh[j], sBh + col * PAD + ks * 16, PAD);
                wmma::load_matrix_sync(bl[j], sBl + col * PAD + ks * 16, PAD);
            }
#pragma unroll
            for (int i = 0; i < 4; i++)
#pragma unroll
                for (int j = 0; j < 2; j++) {
                    wmma::mma_sync(acc[i][j], ah[i], bh[j], acc[i][j]);
                    wmma::mma_sync(acc[i][j], ah[i], bl[j], acc[i][j]);
                    wmma::mma_sync(acc[i][j], al[i], bh[j], acc[i][j]);
                }
        }
        __syncthreads();
    }

    float* epi = (float*)(smem) + w * 256;
#pragma unroll
    for (int i = 0; i < 4; i++)
#pragma unroll
        for (int j = 0; j < 2; j++) {
            const int gcol0 = n0 + wc * 32 + j * 16;
            if (gcol0 < N) {
                wmma::store_matrix_sync(epi, acc[i][j], 16, wmma::mem_row_major);
                __syncwarp();
                const int row  = lane >> 1;
                const int coff = (lane & 1) * 8;
                const int grow = m0 + wr * 64 + i * 16 + row;
                const int gcol = gcol0 + coff;
                float4 b0 = *(const float4*)(bias + gcol);
                float4 b1 = *(const float4*)(bias + gcol + 4);
                const float* e = epi + row * 16 + coff;
                float4 v0 = make_float4(e[0] + b0.x, e[1] + b0.y, e[2] + b0.z, e[3] + b0.w);
                float4 v1 = make_float4(e[4] + b1.x, e[5] + b1.y, e[6] + b1.z, e[7] + b1.w);
                float* cp = C + (size_t)grow * ldc + gcol;
                *(float4*)cp       = v0;
                *(float4*)(cp + 4) = v1;
                __syncwarp();
            }
        }
}

// ============================================================================
// WMMA flash attention (causal), split-bf16 QK^T and PV, fp32 softmax/O.
// 64 q-rows x 64 k-cols tiles, HD=128, 256 threads.
// ============================================================================
#define FQ_LD 136
#define FS_LD 68
#define FP_LD 72
#define FO_LD 132
#define QH_OFF 0
#define QL_OFF 17408
#define KH_OFF 34816
#define KL_OFF 52224
#define VH_OFF 69632
#define VL_OFF 87040
#define S_OFF  104448
#define PH_OFF 121856
#define PL_OFF 131072
#define OT_OFF 140288
#define FLASH_SMEM 174080

__global__ __launch_bounds__(256, 1) void flash_kernel()
{
    extern __shared__ char sm[];
    const uint32_t sb = smem_u32(sm);
    __nv_bfloat16* Qh = (__nv_bfloat16*)(sm + QH_OFF);
    __nv_bfloat16* Ql = (__nv_bfloat16*)(sm + QL_OFF);
    __nv_bfloat16* Kh = (__nv_bfloat16*)(sm + KH_OFF);
    __nv_bfloat16* Kl = (__nv_bfloat16*)(sm + KL_OFF);
    __nv_bfloat16* Vh = (__nv_bfloat16*)(sm + VH_OFF);
    __nv_bfloat16* Vl = (__nv_bfloat16*)(sm + VL_OFF);
    float*         Ss = (float*)(sm + S_OFF);
    __nv_bfloat16* Ph = (__nv_bfloat16*)(sm + PH_OFF);
    __nv_bfloat16* Pl = (__nv_bfloat16*)(sm + PL_OFF);
    float*         Ot = (float*)(sm + OT_OFF);

    const int qt = blockIdx.x;
    const int h  = blockIdx.y;
    const int b  = blockIdx.z;
    const int q0 = qt * 64;
    const int t  = threadIdx.x;
    const int tx = t & 15;
    const int ty = t >> 4;
    const int w  = t >> 5;
    const int wr = w >> 1;          // 0..3 (16 rows)
    const int wc = w & 1;           // 0..1

    // load Q tile (cp.async)
    for (int i = t; i < 1024; i += 256) {
        const int r = i >> 4;
        const int c = (i & 15) << 3;
        const size_t g = (size_t)(b * SS + q0 + r) * HH + h * HDIM + c;
        const uint32_t so = (uint32_t)((r * FQ_LD + c) * 2);
        cp16(sb + QH_OFF + so, g_qh + g, 16);
        cp16(sb + QL_OFF + so, g_ql + g, 16);
    }
    cp_commit();

    float m_i[4], l_i[4], O[4][8];
#pragma unroll
    for (int i = 0; i < 4; i++) {
        m_i[i] = -1e30f; l_i[i] = 0.0f;
#pragma unroll
        for (int c = 0; c < 8; c++) O[i][c] = 0.0f;
    }
    const float scale = 0.08838834764831843f;

    for (int kt = 0; kt <= qt; kt++) {
        const int k0 = kt * 64;
        // load K/V tiles
        for (int i = t; i < 1024; i += 256) {
            const int r = i >> 4;
            const int c = (i & 15) << 3;
            const size_t g = (size_t)(b * SS + k0 + r) * HH + h * HDIM + c;
            const uint32_t so = (uint32_t)((r * FQ_LD + c) * 2);
            cp16(sb + KH_OFF + so, g_kh + g, 16);
            cp16(sb + KL_OFF + so, g_kl + g, 16);
            cp16(sb + VH_OFF + so, g_vrh + g, 16);
            cp16(sb + VL_OFF + so, g_vrl + g, 16);
        }
        cp_commit();
        cp_wait<0>();
        __syncthreads();

        // ---- S = Q K^T ----
        {
            wmma::fragment<wmma::accumulator, 16, 16, 16, float> sacc[2];
            wmma::fill_fragment(sacc[0], 0.0f);
            wmma::fill_fragment(sacc[1], 0.0f);
#pragma unroll
            for (int k = 0; k < 8; k++) {
                wmma::fragment<wmma::matrix_a, 16, 16, 16, __nv_bfloat16, wmma::row_major> ah, al;
                wmma::load_matrix_sync(ah, Qh + (wr * 16) * FQ_LD + k * 16, FQ_LD);
                wmma::load_matrix_sync(al, Ql + (wr * 16) * FQ_LD + k * 16, FQ_LD);
#pragma unroll
                for (int jj = 0; jj < 2; jj++) {
                    const int col0 = wc * 32 + jj * 16;
                    wmma::fragment<wmma::matrix_b, 16, 16, 16, __nv_bfloat16, wmma::col_major> bh, bl;
                    wmma::load_matrix_sync(bh, Kh + col0 * FQ_LD + k * 16, FQ_LD);
                    wmma::load_matrix_sync(bl, Kl + col0 * FQ_LD + k * 16, FQ_LD);
                    wmma::mma_sync(sacc[jj], ah, bh, sacc[jj]);
                    wmma::mma_sync(sacc[jj], al, bh, sacc[jj]);
                    wmma::mma_sync(sacc[jj], ah, bl, sacc[jj]);
                }
            }
#pragma unroll
            for (int jj = 0; jj < 2; jj++)
                wmma::store_matrix_sync(&Ss[(wr * 16) * FS_LD + wc * 32 + jj * 16],
                                        sacc[jj], FS_LD, wmma::mem_row_major);
        }
        __syncthreads();

        // ---- online softmax (per-thread, rows ty*4+i, cols tx+16j) ----
        float corr[4];
#pragma unroll
        for (int i = 0; i < 4; i++) {
            const int row = ty * 4 + i;
            const int qg  = q0 + row;
            float sv[4], rmax = -1e30f;
#pragma unroll
            for (int j = 0; j < 4; j++) {
                float s = Ss[row * FS_LD + tx + 16 * j] * scale;
                if (k0 + tx + 16 * j > qg) s = -1e30f;
                sv[j] = s;
                rmax = fmaxf(rmax, s);
            }
#pragma unroll
            for (int off = 8; off >= 1; off >>= 1)
                rmax = fmaxf(rmax, __shfl_xor_sync(0xffffffffu, rmax, off));
            const float mnew = fmaxf(m_i[i], rmax);
            corr[i] = __expf(m_i[i] - mnew);
            float rsum = 0.0f;
#pragma unroll
            for (int j = 0; j < 4; j++) {
                const float p = __expf(sv[j] - mnew);
                __nv_bfloat16 ph, pl;
                split1(p, ph, pl);
                Ph[row * FP_LD + tx + 16 * j] = ph;
                Pl[row * FP_LD + tx + 16 * j] = pl;
                rsum += p;
            }
#pragma unroll
            for (int off = 8; off >= 1; off >>= 1)
                rsum += __shfl_xor_sync(0xffffffffu, rsum, off);
            l_i[i] = l_i[i] * corr[i] + rsum;
            m_i[i] = mnew;
        }
        __syncthreads();

        // ---- Otmp = P V ----
        {
            wmma::fragment<wmma::accumulator, 16, 16, 16, float> oacc[4];
#pragma unroll
            for (int jj = 0; jj < 4; jj++) wmma::fill_fragment(oacc[jj], 0.0f);
#pragma unroll
            for (int k = 0; k < 4; k++) {
                wmma::fragment<wmma::matrix_a, 16, 16, 16, __nv_bfloat16, wmma::row_major> pah, pal;
                wmma::load_matrix_sync(pah, Ph + (wr * 16) * FP_LD + k * 16, FP_LD);
                wmma::load_matrix_sync(pal, Pl + (wr * 16) * FP_LD + k * 16, FP_LD);
#pragma unroll
                for (int jj = 0; jj < 4; jj++) {
                    const int col0 = wc * 64 + jj * 16;
                    wmma::fragment<wmma::matrix_b, 16, 16, 16, __nv_bfloat16, wmma::row_major> vbh, vbl;
                    wmma::load_matrix_sync(vbh, Vh + (k * 16) * FQ_LD + col0, FQ_LD);
                    wmma::load_matrix_sync(vbl, Vl + (k * 16) * FQ_LD + col0, FQ_LD);
                    wmma::mma_sync(oacc[jj], pah, vbh, oacc[jj]);
                    wmma::mma_sync(oacc[jj], pal, vbh, oacc[jj]);
                    wmma::mma_sync(oacc[jj], pah, vbl, oacc[jj]);
                }
            }
#pragma unroll
            for (int jj = 0; jj < 4; jj++)
                wmma::store_matrix_sync(&Ot[(wr * 16) * FO_LD + wc * 64 + jj * 16],
                                        oacc[jj], FO_LD, wmma::mem_row_major);
        }
        __syncthreads();

        // ---- merge into per-thread O registers ----
#pragma unroll
        for (int i = 0; i < 4; i++) {
            const int row = ty * 4 + i;
#pragma unroll
            for (int c = 0; c < 8; c++)
                O[i][c] = O[i][c] * corr[i] + Ot[row * FO_LD + tx * 8 + c];
        }
    }

    // epilogue: O / l -> bf16 hi/lo directly into g_ath/g_atl
#pragma unroll
    for (int i = 0; i < 4; i++) {
        const float inv = 1.0f / l_i[i];
        const int qg = q0 + ty * 4 + i;
        const size_t o = (size_t)(b * SS + qg) * HH + h * HDIM + tx * 8;
#pragma unroll
        for (int c = 0; c < 8; c += 2) {
            __nv_bfloat16 h0, h1, l0, l1;
            split1(O[i][c] * inv, h0, l0);
            split1(O[i][c + 1] * inv, h1, l1);
            *(__nv_bfloat162*)(g_ath + o + c) = __nv_bfloat162(h0, h1);
            *(__nv_bfloat162*)(g_atl + o + c) = __nv_bfloat162(l0, l1);
        }
    }
}

// ============================================================================
// Launch
// ============================================================================
static inline void split_launch(const float* s, __nv_bfloat16* h, __nv_bfloat16* l, int n)
{
    split_kernel<<<(n / 4 + 255) / 256, 256>>>(s, h, l, n);
}

extern "C" void kernel_launch(void* const* d_in, const int* in_sizes, int n_in,
                              void* d_out, int out_size)
{
    const float* x    = (const float*)d_in[0];
    const float* Wqkv = (const float*)d_in[1];
    const float* bqkv = (const float*)d_in[2];
    const float* Wc   = (const float*)d_in[3];
    const float* bc   = (const float*)d_in[4];
    const float* Wr   = (const float*)d_in[5];
    const float* br   = (const float*)d_in[6];
    const float* Wd   = (const float*)d_in[7];
    const float* bd   = (const float*)d_in[8];
    float* out = (float*)d_out;

    float *qkv, *vc, *vr;
    cudaGetSymbolAddress((void**)&qkv, g_qkv);
    cudaGetSymbolAddress((void**)&vc,  g_vc);
    cudaGetSymbolAddress((void**)&vr,  g_vr);
    __nv_bfloat16 *xh, *xl, *wqh, *wql, *vh, *vl, *wch, *wcl,
                  *vch, *vcl, *wrh, *wrl, *ath, *atl, *wdh, *wdl, *vrh, *vrl;
    cudaGetSymbolAddress((void**)&xh,  g_xh);  cudaGetSymbolAddress((void**)&xl,  g_xl);
    cudaGetSymbolAddress((void**)&wqh, g_wqh); cudaGetSymbolAddress((void**)&wql, g_wql);
    cudaGetSymbolAddress((void**)&vh,  g_vh);  cudaGetSymbolAddress((void**)&vl,  g_vl);
    cudaGetSymbolAddress((void**)&wch, g_wch); cudaGetSymbolAddress((void**)&wcl, g_wcl);
    cudaGetSymbolAddress((void**)&vch, g_vch); cudaGetSymbolAddress((void**)&vcl, g_vcl);
    cudaGetSymbolAddress((void**)&wrh, g_wrh); cudaGetSymbolAddress((void**)&wrl, g_wrl);
    cudaGetSymbolAddress((void**)&ath, g_ath); cudaGetSymbolAddress((void**)&atl, g_atl);
    cudaGetSymbolAddress((void**)&wdh, g_wdh); cudaGetSymbolAddress((void**)&wdl, g_wdl);
    cudaGetSymbolAddress((void**)&vrh, g_vrh); cudaGetSymbolAddress((void**)&vrl, g_vrl);

    cudaFuncSetAttribute(gemm_wmma_kernel,
                         cudaFuncAttributeMaxDynamicSharedMemorySize, GEMM_SMEM);
    cudaFuncSetAttribute(flash_kernel,
                         cudaFuncAttributeMaxDynamicSharedMemorySize, FLASH_SMEM);

    // 1. qkv = x @ Wqkv^T + bqkv
    split_launch(x, xh, xl, MALL * HH);
    split_launch(Wqkv, wqh, wql, H3 * HH);
    gemm_wmma_kernel<<<dim3(H3 / 128, MALL / 128), 256, GEMM_SMEM>>>(
        xh, xl, wqh, wql, bqkv, qkv, H3, H3, HH);

    // 2. fused RoPE + q/k split
    rope_split_kernel<<<BB * SS * NHEAD / 8, 256>>>();

    // 3. vc = v @ Wc^T + bc
    split_v_kernel<<<(MALL * HH / 4 + 255) / 256, 256>>>();
    split_launch(Wc, wch, wcl, VP * HH);
    gemm_wmma_kernel<<<dim3((VP + 127) / 128, MALL / 128), 256, GEMM_SMEM>>>(
        vh, vl, wch, wcl, bc, vc, VP, VP, HH);

    // 4. vr = vc @ Wr^T + br
    split_launch(vc, vch, vcl, MALL * VP);
    split_launch(Wr, wrh, wrl, HH * VP);
    gemm_wmma_kernel<<<dim3(HH / 128, MALL / 128), 256, GEMM_SMEM>>>(
        vch, vcl, wrh, wrl, br, vr, HH, HH, VP);
    split_launch(vr, vrh, vrl, MALL * HH);

    // 5. flash attention (WMMA) -> ath/atl directly
    flash_kernel<<<dim3(SS / 64, NHEAD, BB), 256, FLASH_SMEM>>>();

    // 6. out = att @ Wd^T + bd
    split_launch(Wd, wdh, wdl, HH * HH);
    gemm_wmma_kernel<<<dim3(HH / 128, MALL / 128), 256, GEMM_SMEM>>>(
        ath, atl, wdh, wdl, bd, out, HH, HH, HH);
}

// round 7
// speedup vs baseline: 2.1371x; 1.0847x over previous
#include <cuda_runtime.h>
#include <cuda_bf16.h>
#include <mma.h>
#include <math.h>
#include <stdint.h>

using namespace nvcuda;

// Problem constants
#define BB 2
#define SS 2048
#define HH 2048
#define NHEAD 16
#define HDIM 128
#define H3 6144
#define VP 320
#define MALL 4096

// -------- fp32 scratch --------
__device__ float g_qkv[BB * SS * H3];

// -------- bf16 hi/lo scratch --------
__device__ __nv_bfloat16 g_xh [MALL * HH],  g_xl [MALL * HH];
__device__ __nv_bfloat16 g_wqh[H3 * HH],    g_wql[H3 * HH];
__device__ __nv_bfloat16 g_vh [MALL * HH],  g_vl [MALL * HH];   // v slice (Vc input)
__device__ __nv_bfloat16 g_wch[VP * HH],    g_wcl[VP * HH];
__device__ __nv_bfloat16 g_vch[MALL * VP],  g_vcl[MALL * VP];
__device__ __nv_bfloat16 g_wrh[HH * VP],    g_wrl[HH * VP];
__device__ __nv_bfloat16 g_ath[MALL * HH],  g_atl[MALL * HH];
__device__ __nv_bfloat16 g_wdh[HH * HH],    g_wdl[HH * HH];
__device__ __nv_bfloat16 g_qh [MALL * HH],  g_ql [MALL * HH];
__device__ __nv_bfloat16 g_kh [MALL * HH],  g_kl [MALL * HH];
__device__ __nv_bfloat16 g_vrh[MALL * HH],  g_vrl[MALL * HH];

// ============================================================================
// helpers
// ============================================================================
__device__ __forceinline__ uint32_t smem_u32(const void* p) {
    uint32_t a;
    asm("{ .reg .u64 t; cvta.to.shared.u64 t, %1; cvt.u32.u64 %0, t; }"
        : "=r"(a) : "l"(p));
    return a;
}
__device__ __forceinline__ void cp16(uint32_t s, const void* g, uint32_t nbytes) {
    asm volatile("cp.async.cg.shared.global [%0], [%1], 16, %2;"
                 :: "r"(s), "l"(g), "r"(nbytes) : "memory");
}
__device__ __forceinline__ void cp_commit() {
    asm volatile("cp.async.commit_group;" ::: "memory");
}
template <int N>
__device__ __forceinline__ void cp_wait() {
    asm volatile("cp.async.wait_group %0;" :: "n"(N) : "memory");
}
__device__ __forceinline__ void split1(float v, __nv_bfloat16& h, __nv_bfloat16& l) {
    h = __float2bfloat16(v);
    l = __float2bfloat16(v - __bfloat162float(h));
}
__device__ __forceinline__ uint32_t pack2(__nv_bfloat16 a, __nv_bfloat16 b) {
    return (uint32_t)__bfloat16_as_ushort(a) |
           ((uint32_t)__bfloat16_as_ushort(b) << 16);
}

// ============================================================================
// fp32 -> bf16 (hi, lo) split
// ============================================================================
__global__ void split_kernel(const float* __restrict__ src,
                             __nv_bfloat16* __restrict__ hi,
                             __nv_bfloat16* __restrict__ lo, int n)
{
    int i = (blockIdx.x * blockDim.x + threadIdx.x) * 4;
    if (i >= n) return;
    float4 v = *(const float4*)(src + i);
    __nv_bfloat16 h0, h1, h2, h3, l0, l1, l2, l3;
    split1(v.x, h0, l0); split1(v.y, h1, l1);
    split1(v.z, h2, l2); split1(v.w, h3, l3);
    *(uint2*)(hi + i) = make_uint2(pack2(h0, h1), pack2(h2, h3));
    *(uint2*)(lo + i) = make_uint2(pack2(l0, l1), pack2(l2, l3));
}

// v slice of g_qkv (strided) -> contiguous bf16 hi/lo [MALL x HH]
__global__ void split_v_kernel()
{
    int i = (blockIdx.x * blockDim.x + threadIdx.x) * 4;
    if (i >= MALL * HH) return;
    int r = i / HH, c = i % HH;
    float4 v = *(const float4*)(g_qkv + (size_t)r * H3 + 2 * HH + c);
    __nv_bfloat16 h0, h1, h2, h3, l0, l1, l2, l3;
    split1(v.x, h0, l0); split1(v.y, h1, l1);
    split1(v.z, h2, l2); split1(v.w, h3, l3);
    *(uint2*)(g_vh + i) = make_uint2(pack2(h0, h1), pack2(h2, h3));
    *(uint2*)(g_vl + i) = make_uint2(pack2(l0, l1), pack2(l2, l3));
}

// ============================================================================
// fused RoPE + split for q, k
// ============================================================================
__global__ void rope_split_kernel()
{
    const int gw   = blockIdx.x * 8 + (threadIdx.x >> 5);
    const int lane = threadIdx.x & 31;
    const int h = gw & 15;
    const int s = (gw >> 4) & 2047;
    const int b = gw >> 15;

    const size_t qbase = (size_t)(b * SS + s) * H3 + h * HDIM;
    const int d0 = lane * 4;
    float4 q = *(const float4*)(g_qkv + qbase + d0);
    float4 k = *(const float4*)(g_qkv + qbase + HH + d0);

    float4 qp, kp;
    qp.x = __shfl_xor_sync(0xffffffffu, q.x, 4);
    qp.y = __shfl_xor_sync(0xffffffffu, q.y, 4);
    qp.z = __shfl_xor_sync(0xffffffffu, q.z, 4);
    qp.w = __shfl_xor_sync(0xffffffffu, q.w, 4);
    kp.x = __shfl_xor_sync(0xffffffffu, k.x, 4);
    kp.y = __shfl_xor_sync(0xffffffffu, k.y, 4);
    kp.z = __shfl_xor_sync(0xffffffffu, k.z, 4);
    kp.w = __shfl_xor_sync(0xffffffffu, k.w, 4);

    if (lane < 8) {
        const float sgn = (lane < 4) ? -1.0f : 1.0f;
        float qa[4] = {q.x, q.y, q.z, q.w};
        float pa[4] = {qp.x, qp.y, qp.z, qp.w};
        float ka[4] = {k.x, k.y, k.z, k.w};
        float kb[4] = {kp.x, kp.y, kp.z, kp.w};
#pragma unroll
        for (int i = 0; i < 4; i++) {
            int j = (lane & 3) * 4 + i;
            float inv = __expf(-(float)(2 * j) * (9.210340371976184f / 32.0f));
            float sn, cs;
            sincosf((float)s * inv, &sn, &cs);
            qa[i] = qa[i] * cs + sgn * pa[i] * sn;
            ka[i] = ka[i] * cs + sgn * kb[i] * sn;
        }
        q = make_float4(qa[0], qa[1], qa[2], qa[3]);
        k = make_float4(ka[0], ka[1], ka[2], ka[3]);
    }

    const size_t o = (size_t)(b * SS + s) * HH + h * HDIM + d0;
    __nv_bfloat16 h0, h1, h2, h3, l0, l1, l2, l3;
    split1(q.x, h0, l0); split1(q.y, h1, l1);
    split1(q.z, h2, l2); split1(q.w, h3, l3);
    *(uint2*)(g_qh + o) = make_uint2(pack2(h0, h1), pack2(h2, h3));
    *(uint2*)(g_ql + o) = make_uint2(pack2(l0, l1), pack2(l2, l3));
    split1(k.x, h0, l0); split1(k.y, h1, l1);
    split1(k.z, h2, l2); split1(k.w, h3, l3);
    *(uint2*)(g_kh + o) = make_uint2(pack2(h0, h1), pack2(h2, h3));
    *(uint2*)(g_kl + o) = make_uint2(pack2(l0, l1), pack2(l2, l3));
}

// ============================================================================
// WMMA split-bf16 GEMM, 128(M) x 256(N) CTA tile, 64x64 per warp (2x4 warps),
// K-chunk 32, 2-stage cp.async pipeline.
// mode: writes fp32 C (Chi==null) or bf16 hi/lo pair (Chi/Clo != null).
// ============================================================================
#define PADE    40                        // smem row stride in bf16 elems
#define A_TILE  (128 * PADE * 2)          // 10240 B
#define B_TILE  (256 * PADE * 2)          // 20480 B
#define STAGE_SM (2 * A_TILE + 2 * B_TILE)  // 61440 B: Ah, Al, Bh, Bl
#define GEMM_SMEM (2 * STAGE_SM)            // 122880 B

__global__ __launch_bounds__(256, 1) void gemm_wmma_kernel(
    const __nv_bfloat16* __restrict__ Ah, const __nv_bfloat16* __restrict__ Al,
    const __nv_bfloat16* __restrict__ Bh, const __nv_bfloat16* __restrict__ Bl,
    const float* __restrict__ bias,
    float* __restrict__ C,
    __nv_bfloat16* __restrict__ Chi, __nv_bfloat16* __restrict__ Clo,
    int ldc, int N, int K)
{
    extern __shared__ char smem[];
    const uint32_t sbase = smem_u32(smem);
    const int t    = threadIdx.x;
    const int w    = t >> 5;
    const int lane = t & 31;
    const int wm   = w >> 2;     // 0..1
    const int wn   = w & 3;      // 0..3
    const int m0   = blockIdx.y * 128;
    const int n0   = blockIdx.x * 256;

    wmma::fragment<wmma::accumulator, 16, 16, 16, float> acc[4][4];
#pragma unroll
    for (int i = 0; i < 4; i++)
#pragma unroll
        for (int j = 0; j < 4; j++) wmma::fill_fragment(acc[i][j], 0.0f);

    const int nchunks = K / 32;

    auto load_stage = [&](int chunk, int stage) {
        const int kk = chunk * 32;
        const uint32_t sst = sbase + stage * STAGE_SM;
        // A tiles: 2 x 512 cp16
#pragma unroll
        for (int rep = 0; rep < 4; rep++) {
            const int v = t + rep * 256;            // 0..1023
            const int tile = v >> 9;                // 0=Ah, 1=Al
            const int r = (v >> 2) & 127;
            const int c = (v & 3) * 8;
            const __nv_bfloat16* src = tile ? Al : Ah;
            cp16(sst + tile * A_TILE + r * (PADE * 2) + c * 2,
                 src + (size_t)(m0 + r) * K + kk + c, 16);
        }
        // B tiles: 2 x 1024 cp16
#pragma unroll
        for (int rep = 0; rep < 8; rep++) {
            const int v = t + rep * 256;            // 0..2047
            const int tile = v >> 10;               // 0=Bh, 1=Bl
            const int r = (v >> 2) & 255;
            const int c = (v & 3) * 8;
            const __nv_bfloat16* src = tile ? Bl : Bh;
            const int brow = n0 + r;
            const uint32_t vb = (brow < N) ? 16u : 0u;
            cp16(sst + 2 * A_TILE + tile * B_TILE + r * (PADE * 2) + c * 2,
                 src + (size_t)(brow < N ? brow : 0) * K + kk + c, vb);
        }
        cp_commit();
    };

    load_stage(0, 0);

    for (int chunk = 0; chunk < nchunks; chunk++) {
        const int stage = chunk & 1;
        if (chunk + 1 < nchunks) { load_stage(chunk + 1, stage ^ 1); cp_wait<1>(); }
        else cp_wait<0>();
        __syncthreads();

        const __nv_bfloat16* sAh = (const __nv_bfloat16*)(smem + stage * STAGE_SM);
        const __nv_bfloat16* sAl = (const __nv_bfloat16*)(smem + stage * STAGE_SM + A_TILE);
        const __nv_bfloat16* sBh = (const __nv_bfloat16*)(smem + stage * STAGE_SM + 2 * A_TILE);
        const __nv_bfloat16* sBl = (const __nv_bfloat16*)(smem + stage * STAGE_SM + 2 * A_TILE + B_TILE);

#pragma unroll
        for (int ks = 0; ks < 2; ks++) {
            wmma::fragment<wmma::matrix_a, 16, 16, 16, __nv_bfloat16, wmma::row_major> ah[4], al[4];
#pragma unroll
            for (int i = 0; i < 4; i++) {
                const int row = wm * 64 + i * 16;
                wmma::load_matrix_sync(ah[i], sAh + row * PADE + ks * 16, PADE);
                wmma::load_matrix_sync(al[i], sAl + row * PADE + ks * 16, PADE);
            }
#pragma unroll
            for (int j = 0; j < 4; j++) {
                const int col = wn * 64 + j * 16;
                wmma::fragment<wmma::matrix_b, 16, 16, 16, __nv_bfloat16, wmma::col_major> bh, bl;
                wmma::load_matrix_sync(bh, sBh + col * PADE + ks * 16, PADE);
                wmma::load_matrix_sync(bl, sBl + col * PADE + ks * 16, PADE);
#pragma unroll
                for (int i = 0; i < 4; i++) {
                    wmma::mma_sync(acc[i][j], ah[i], bh, acc[i][j]);
                    wmma::mma_sync(acc[i][j], ah[i], bl, acc[i][j]);
                    wmma::mma_sync(acc[i][j], al[i], bh, acc[i][j]);
                }
            }
        }
        __syncthreads();
    }

    // epilogue
    float* epi = (float*)(smem) + w * 256;
#pragma unroll
    for (int i = 0; i < 4; i++)
#pragma unroll
        for (int j = 0; j < 4; j++) {
            const int gcol0 = n0 + wn * 64 + j * 16;
            if (gcol0 < N) {
                wmma::store_matrix_sync(epi, acc[i][j], 16, wmma::mem_row_major);
                __syncwarp();
                const int row  = lane >> 1;
                const int coff = (lane & 1) * 8;
                const int grow = m0 + wm * 64 + i * 16 + row;
                const int gcol = gcol0 + coff;
                float4 b0 = *(const float4*)(bias + gcol);
                float4 b1 = *(const float4*)(bias + gcol + 4);
                const float* e = epi + row * 16 + coff;
                float vals[8] = {e[0] + b0.x, e[1] + b0.y, e[2] + b0.z, e[3] + b0.w,
                                 e[4] + b1.x, e[5] + b1.y, e[6] + b1.z, e[7] + b1.w};
                if (Chi == nullptr) {
                    float* cp = C + (size_t)grow * ldc + gcol;
                    *(float4*)cp       = make_float4(vals[0], vals[1], vals[2], vals[3]);
                    *(float4*)(cp + 4) = make_float4(vals[4], vals[5], vals[6], vals[7]);
                } else {
                    __nv_bfloat16 hh[8], ll[8];
#pragma unroll
                    for (int c = 0; c < 8; c++) split1(vals[c], hh[c], ll[c]);
                    uint4 uh = make_uint4(pack2(hh[0], hh[1]), pack2(hh[2], hh[3]),
                                          pack2(hh[4], hh[5]), pack2(hh[6], hh[7]));
                    uint4 ul = make_uint4(pack2(ll[0], ll[1]), pack2(ll[2], ll[3]),
                                          pack2(ll[4], ll[5]), pack2(ll[6], ll[7]));
                    *(uint4*)(Chi + (size_t)grow * ldc + gcol) = uh;
                    *(uint4*)(Clo + (size_t)grow * ldc + gcol) = ul;
                }
                __syncwarp();
            }
        }
}

// ============================================================================
// WMMA flash attention (causal), split-bf16 QK^T and PV, fp32 softmax/O.
// K load and V load in separate commit groups: V overlaps softmax.
// ============================================================================
#define FQ_LD 136
#define FS_LD 68
#define FP_LD 72
#define FO_LD 132
#define QH_OFF 0
#define QL_OFF 17408
#define KH_OFF 34816
#define KL_OFF 52224
#define VH_OFF 69632
#define VL_OFF 87040
#define S_OFF  104448
#define PH_OFF 121856
#define PL_OFF 131072
#define OT_OFF 140288
#define FLASH_SMEM 174080

__global__ __launch_bounds__(256, 1) void flash_kernel()
{
    extern __shared__ char sm[];
    const uint32_t sb = smem_u32(sm);
    __nv_bfloat16* Qh = (__nv_bfloat16*)(sm + QH_OFF);
    __nv_bfloat16* Ql = (__nv_bfloat16*)(sm + QL_OFF);
    __nv_bfloat16* Kh = (__nv_bfloat16*)(sm + KH_OFF);
    __nv_bfloat16* Kl = (__nv_bfloat16*)(sm + KL_OFF);
    __nv_bfloat16* Vh = (__nv_bfloat16*)(sm + VH_OFF);
    __nv_bfloat16* Vl = (__nv_bfloat16*)(sm + VL_OFF);
    float*         Ss = (float*)(sm + S_OFF);
    __nv_bfloat16* Ph = (__nv_bfloat16*)(sm + PH_OFF);
    __nv_bfloat16* Pl = (__nv_bfloat16*)(sm + PL_OFF);
    float*         Ot = (float*)(sm + OT_OFF);

    const int qt = blockIdx.x;
    const int h  = blockIdx.y;
    const int b  = blockIdx.z;
    const int q0 = qt * 64;
    const int t  = threadIdx.x;
    const int tx = t & 15;
    const int ty = t >> 4;
    const int w  = t >> 5;
    const int wr = w >> 1;
    const int wc = w & 1;

    for (int i = t; i < 1024; i += 256) {
        const int r = i >> 4;
        const int c = (i & 15) << 3;
        const size_t g = (size_t)(b * SS + q0 + r) * HH + h * HDIM + c;
        const uint32_t so = (uint32_t)((r * FQ_LD + c) * 2);
        cp16(sb + QH_OFF + so, g_qh + g, 16);
        cp16(sb + QL_OFF + so, g_ql + g, 16);
    }
    cp_commit();

    float m_i[4], l_i[4], O[4][8];
#pragma unroll
    for (int i = 0; i < 4; i++) {
        m_i[i] = -1e30f; l_i[i] = 0.0f;
#pragma unroll
        for (int c = 0; c < 8; c++) O[i][c] = 0.0f;
    }
    const float scale = 0.08838834764831843f;

    for (int kt = 0; kt <= qt; kt++) {
        const int k0 = kt * 64;
        // K tiles
        for (int i = t; i < 1024; i += 256) {
            const int r = i >> 4;
            const int c = (i & 15) << 3;
            const size_t g = (size_t)(b * SS + k0 + r) * HH + h * HDIM + c;
            const uint32_t so = (uint32_t)((r * FQ_LD + c) * 2);
            cp16(sb + KH_OFF + so, g_kh + g, 16);
            cp16(sb + KL_OFF + so, g_kl + g, 16);
        }
        cp_commit();
        // V tiles (separate group, overlaps QK^T + softmax)
        for (int i = t; i < 1024; i += 256) {
            const int r = i >> 4;
            const int c = (i & 15) << 3;
            const size_t g = (size_t)(b * SS + k0 + r) * HH + h * HDIM + c;
            const uint32_t so = (uint32_t)((r * FQ_LD + c) * 2);
            cp16(sb + VH_OFF + so, g_vrh + g, 16);
            cp16(sb + VL_OFF + so, g_vrl + g, 16);
        }
        cp_commit();
        cp_wait<1>();          // K (and Q on first iter) ready; V may be in flight
        __syncthreads();

        // ---- S = Q K^T ----
        {
            wmma::fragment<wmma::accumulator, 16, 16, 16, float> sacc[2];
            wmma::fill_fragment(sacc[0], 0.0f);
            wmma::fill_fragment(sacc[1], 0.0f);
#pragma unroll
            for (int k = 0; k < 8; k++) {
                wmma::fragment<wmma::matrix_a, 16, 16, 16, __nv_bfloat16, wmma::row_major> ah, al;
                wmma::load_matrix_sync(ah, Qh + (wr * 16) * FQ_LD + k * 16, FQ_LD);
                wmma::load_matrix_sync(al, Ql + (wr * 16) * FQ_LD + k * 16, FQ_LD);
#pragma unroll
                for (int jj = 0; jj < 2; jj++) {
                    const int col0 = wc * 32 + jj * 16;
                    wmma::fragment<wmma::matrix_b, 16, 16, 16, __nv_bfloat16, wmma::col_major> bh, bl;
                    wmma::load_matrix_sync(bh, Kh + col0 * FQ_LD + k * 16, FQ_LD);
                    wmma::load_matrix_sync(bl, Kl + col0 * FQ_LD + k * 16, FQ_LD);
                    wmma::mma_sync(sacc[jj], ah, bh, sacc[jj]);
                    wmma::mma_sync(sacc[jj], al, bh, sacc[jj]);
                    wmma::mma_sync(sacc[jj], ah, bl, sacc[jj]);
                }
            }
#pragma unroll
            for (int jj = 0; jj < 2; jj++)
                wmma::store_matrix_sync(&Ss[(wr * 16) * FS_LD + wc * 32 + jj * 16],
                                        sacc[jj], FS_LD, wmma::mem_row_major);
        }
        __syncthreads();

        // ---- online softmax ----
        float corr[4];
#pragma unroll
        for (int i = 0; i < 4; i++) {
            const int row = ty * 4 + i;
            const int qg  = q0 + row;
            float sv[4], rmax = -1e30f;
#pragma unroll
            for (int j = 0; j < 4; j++) {
                float s = Ss[row * FS_LD + tx + 16 * j] * scale;
                if (k0 + tx + 16 * j > qg) s = -1e30f;
                sv[j] = s;
                rmax = fmaxf(rmax, s);
            }
#pragma unroll
            for (int off = 8; off >= 1; off >>= 1)
                rmax = fmaxf(rmax, __shfl_xor_sync(0xffffffffu, rmax, off));
            const float mnew = fmaxf(m_i[i], rmax);
            corr[i] = __expf(m_i[i] - mnew);
            float rsum = 0.0f;
#pragma unroll
            for (int j = 0; j < 4; j++) {
                const float p = __expf(sv[j] - mnew);
                __nv_bfloat16 ph, pl;
                split1(p, ph, pl);
                Ph[row * FP_LD + tx + 16 * j] = ph;
                Pl[row * FP_LD + tx + 16 * j] = pl;
                rsum += p;
            }
#pragma unroll
            for (int off = 8; off >= 1; off >>= 1)
                rsum += __shfl_xor_sync(0xffffffffu, rsum, off);
            l_i[i] = l_i[i] * corr[i] + rsum;
            m_i[i] = mnew;
        }
        cp_wait<0>();          // V ready
        __syncthreads();

        // ---- Otmp = P V ----
        {
            wmma::fragment<wmma::accumulator, 16, 16, 16, float> oacc[4];
#pragma unroll
            for (int jj = 0; jj < 4; jj++) wmma::fill_fragment(oacc[jj], 0.0f);
#pragma unroll
            for (int k = 0; k < 4; k++) {
                wmma::fragment<wmma::matrix_a, 16, 16, 16, __nv_bfloat16, wmma::row_major> pah, pal;
                wmma::load_matrix_sync(pah, Ph + (wr * 16) * FP_LD + k * 16, FP_LD);
                wmma::load_matrix_sync(pal, Pl + (wr * 16) * FP_LD + k * 16, FP_LD);
#pragma unroll
                for (int jj = 0; jj < 4; jj++) {
                    const int col0 = wc * 64 + jj * 16;
                    wmma::fragment<wmma::matrix_b, 16, 16, 16, __nv_bfloat16, wmma::row_major> vbh, vbl;
                    wmma::load_matrix_sync(vbh, Vh + (k * 16) * FQ_LD + col0, FQ_LD);
                    wmma::load_matrix_sync(vbl, Vl + (k * 16) * FQ_LD + col0, FQ_LD);
                    wmma::mma_sync(oacc[jj], pah, vbh, oacc[jj]);
                    wmma::mma_sync(oacc[jj], pal, vbh, oacc[jj]);
                    wmma::mma_sync(oacc[jj], pah, vbl, oacc[jj]);
                }
            }
#pragma unroll
            for (int jj = 0; jj < 4; jj++)
                wmma::store_matrix_sync(&Ot[(wr * 16) * FO_LD + wc * 64 + jj * 16],
                                        oacc[jj], FO_LD, wmma::mem_row_major);
        }
        __syncthreads();

#pragma unroll
        for (int i = 0; i < 4; i++) {
            const int row = ty * 4 + i;
#pragma unroll
            for (int c = 0; c < 8; c++)
                O[i][c] = O[i][c] * corr[i] + Ot[row * FO_LD + tx * 8 + c];
        }
    }

#pragma unroll
    for (int i = 0; i < 4; i++) {
        const float inv = 1.0f / l_i[i];
        const int qg = q0 + ty * 4 + i;
        const size_t o = (size_t)(b * SS + qg) * HH + h * HDIM + tx * 8;
        __nv_bfloat16 hh[8], ll[8];
#pragma unroll
        for (int c = 0; c < 8; c++) split1(O[i][c] * inv, hh[c], ll[c]);
        *(uint4*)(g_ath + o) = make_uint4(pack2(hh[0], hh[1]), pack2(hh[2], hh[3]),
                                          pack2(hh[4], hh[5]), pack2(hh[6], hh[7]));
        *(uint4*)(g_atl + o) = make_uint4(pack2(ll[0], ll[1]), pack2(ll[2], ll[3]),
                                          pack2(ll[4], ll[5]), pack2(ll[6], ll[7]));
    }
}

// ============================================================================
// Launch
// ============================================================================
static inline void split_launch(const float* s, __nv_bfloat16* h, __nv_bfloat16* l, int n)
{
    split_kernel<<<(n / 4 + 255) / 256, 256>>>(s, h, l, n);
}

extern "C" void kernel_launch(void* const* d_in, const int* in_sizes, int n_in,
                              void* d_out, int out_size)
{
    const float* x    = (const float*)d_in[0];
    const float* Wqkv = (const float*)d_in[1];
    const float* bqkv = (const float*)d_in[2];
    const float* Wc   = (const float*)d_in[3];
    const float* bc   = (const float*)d_in[4];
    const float* Wr   = (const float*)d_in[5];
    const float* br   = (const float*)d_in[6];
    const float* Wd   = (const float*)d_in[7];
    const float* bd   = (const float*)d_in[8];
    float* out = (float*)d_out;

    float* qkv;
    cudaGetSymbolAddress((void**)&qkv, g_qkv);
    __nv_bfloat16 *xh, *xl, *wqh, *wql, *vh, *vl, *wch, *wcl,
                  *vch, *vcl, *wrh, *wrl, *ath, *atl, *wdh, *wdl, *vrh, *vrl;
    cudaGetSymbolAddress((void**)&xh,  g_xh);  cudaGetSymbolAddress((void**)&xl,  g_xl);
    cudaGetSymbolAddress((void**)&wqh, g_wqh); cudaGetSymbolAddress((void**)&wql, g_wql);
    cudaGetSymbolAddress((void**)&vh,  g_vh);  cudaGetSymbolAddress((void**)&vl,  g_vl);
    cudaGetSymbolAddress((void**)&wch, g_wch); cudaGetSymbolAddress((void**)&wcl, g_wcl);
    cudaGetSymbolAddress((void**)&vch, g_vch); cudaGetSymbolAddress((void**)&vcl, g_vcl);
    cudaGetSymbolAddress((void**)&wrh, g_wrh); cudaGetSymbolAddress((void**)&wrl, g_wrl);
    cudaGetSymbolAddress((void**)&ath, g_ath); cudaGetSymbolAddress((void**)&atl, g_atl);
    cudaGetSymbolAddress((void**)&wdh, g_wdh); cudaGetSymbolAddress((void**)&wdl, g_wdl);
    cudaGetSymbolAddress((void**)&vrh, g_vrh); cudaGetSymbolAddress((void**)&vrl, g_vrl);

    cudaFuncSetAttribute(gemm_wmma_kernel,
                         cudaFuncAttributeMaxDynamicSharedMemorySize, GEMM_SMEM);
    cudaFuncSetAttribute(flash_kernel,
                         cudaFuncAttributeMaxDynamicSharedMemorySize, FLASH_SMEM);

    // 1. qkv = x @ Wqkv^T + bqkv  (fp32 out; feeds rope + v split)
    split_launch(x, xh, xl, MALL * HH);
    split_launch(Wqkv, wqh, wql, H3 * HH);
    gemm_wmma_kernel<<<dim3(H3 / 256, MALL / 128), 256, GEMM_SMEM>>>(
        xh, xl, wqh, wql, bqkv, qkv, nullptr, nullptr, H3, H3, HH);

    // 2. fused RoPE + q/k split
    rope_split_kernel<<<BB * SS * NHEAD / 8, 256>>>();

    // 3. vc = v @ Wc^T + bc  -> bf16 hi/lo directly
    split_v_kernel<<<(MALL * HH / 4 + 255) / 256, 256>>>();
    split_launch(Wc, wch, wcl, VP * HH);
    gemm_wmma_kernel<<<dim3((VP + 255) / 256, MALL / 128), 256, GEMM_SMEM>>>(
        vh, vl, wch, wcl, bc, nullptr, vch, vcl, VP, VP, HH);

    // 4. vr = vc @ Wr^T + br -> bf16 hi/lo directly
    split_launch(Wr, wrh, wrl, HH * VP);
    gemm_wmma_kernel<<<dim3(HH / 256, MALL / 128), 256, GEMM_SMEM>>>(
        vch, vcl, wrh, wrl, br, nullptr, vrh, vrl, HH, HH, VP);

    // 5. flash attention -> ath/atl
    flash_kernel<<<dim3(SS / 64, NHEAD, BB), 256, FLASH_SMEM>>>();

    // 6. out = att @ Wd^T + bd (fp32)
    split_launch(Wd, wdh, wdl, HH * HH);
    gemm_wmma_kernel<<<dim3(HH / 256, MALL / 128), 256, GEMM_SMEM>>>(
        ath, atl, wdh, wdl, bd, out, nullptr, nullptr, HH, HH, HH);
}

// round 8
// speedup vs baseline: 2.1513x; 1.0066x over previous
#include <cuda_runtime.h>
#include <cuda_bf16.h>
#include <mma.h>
#include <math.h>
#include <stdint.h>

using namespace nvcuda;

// Problem constants
#define BB 2
#define SS 2048
#define HH 2048
#define NHEAD 16
#define HDIM 128
#define H3 6144
#define VP 320
#define MALL 4096

// -------- fp32 scratch --------
__device__ float g_qkv[BB * SS * H3];

// -------- bf16 hi/lo scratch --------
__device__ __nv_bfloat16 g_xh [MALL * HH],  g_xl [MALL * HH];
__device__ __nv_bfloat16 g_wqh[H3 * HH],    g_wql[H3 * HH];
__device__ __nv_bfloat16 g_vh [MALL * HH],  g_vl [MALL * HH];
__device__ __nv_bfloat16 g_wch[VP * HH],    g_wcl[VP * HH];
__device__ __nv_bfloat16 g_vch[MALL * VP],  g_vcl[MALL * VP];
__device__ __nv_bfloat16 g_wrh[HH * VP],    g_wrl[HH * VP];
__device__ __nv_bfloat16 g_ath[MALL * HH],  g_atl[MALL * HH];
__device__ __nv_bfloat16 g_wdh[HH * HH],    g_wdl[HH * HH];
__device__ __nv_bfloat16 g_qh [MALL * HH],  g_ql [MALL * HH];
__device__ __nv_bfloat16 g_kh [MALL * HH],  g_kl [MALL * HH];
__device__ __nv_bfloat16 g_vrh[MALL * HH],  g_vrl[MALL * HH];

// ============================================================================
// helpers
// ============================================================================
__device__ __forceinline__ uint32_t smem_u32(const void* p) {
    uint32_t a;
    asm("{ .reg .u64 t; cvta.to.shared.u64 t, %1; cvt.u32.u64 %0, t; }"
        : "=r"(a) : "l"(p));
    return a;
}
__device__ __forceinline__ void cp16(uint32_t s, const void* g, uint32_t nbytes) {
    asm volatile("cp.async.cg.shared.global [%0], [%1], 16, %2;"
                 :: "r"(s), "l"(g), "r"(nbytes) : "memory");
}
__device__ __forceinline__ void cp_commit() {
    asm volatile("cp.async.commit_group;" ::: "memory");
}
template <int N>
__device__ __forceinline__ void cp_wait() {
    asm volatile("cp.async.wait_group %0;" :: "n"(N) : "memory");
}
__device__ __forceinline__ void split1(float v, __nv_bfloat16& h, __nv_bfloat16& l) {
    h = __float2bfloat16(v);
    l = __float2bfloat16(v - __bfloat162float(h));
}
__device__ __forceinline__ uint32_t pack2(__nv_bfloat16 a, __nv_bfloat16 b) {
    return (uint32_t)__bfloat16_as_ushort(a) |
           ((uint32_t)__bfloat16_as_ushort(b) << 16);
}

// ============================================================================
// fp32 -> bf16 (hi, lo) split
// ============================================================================
__global__ void split_kernel(const float* __restrict__ src,
                             __nv_bfloat16* __restrict__ hi,
                             __nv_bfloat16* __restrict__ lo, int n)
{
    int i = (blockIdx.x * blockDim.x + threadIdx.x) * 4;
    if (i >= n) return;
    float4 v = *(const float4*)(src + i);
    __nv_bfloat16 h0, h1, h2, h3, l0, l1, l2, l3;
    split1(v.x, h0, l0); split1(v.y, h1, l1);
    split1(v.z, h2, l2); split1(v.w, h3, l3);
    *(uint2*)(hi + i) = make_uint2(pack2(h0, h1), pack2(h2, h3));
    *(uint2*)(lo + i) = make_uint2(pack2(l0, l1), pack2(l2, l3));
}

__global__ void split_v_kernel()
{
    int i = (blockIdx.x * blockDim.x + threadIdx.x) * 4;
    if (i >= MALL * HH) return;
    int r = i / HH, c = i % HH;
    float4 v = *(const float4*)(g_qkv + (size_t)r * H3 + 2 * HH + c);
    __nv_bfloat16 h0, h1, h2, h3, l0, l1, l2, l3;
    split1(v.x, h0, l0); split1(v.y, h1, l1);
    split1(v.z, h2, l2); split1(v.w, h3, l3);
    *(uint2*)(g_vh + i) = make_uint2(pack2(h0, h1), pack2(h2, h3));
    *(uint2*)(g_vl + i) = make_uint2(pack2(l0, l1), pack2(l2, l3));
}

// ============================================================================
// fused RoPE + split for q, k
// ============================================================================
__global__ void rope_split_kernel()
{
    const int gw   = blockIdx.x * 8 + (threadIdx.x >> 5);
    const int lane = threadIdx.x & 31;
    const int h = gw & 15;
    const int s = (gw >> 4) & 2047;
    const int b = gw >> 15;

    const size_t qbase = (size_t)(b * SS + s) * H3 + h * HDIM;
    const int d0 = lane * 4;
    float4 q = *(const float4*)(g_qkv + qbase + d0);
    float4 k = *(const float4*)(g_qkv + qbase + HH + d0);

    float4 qp, kp;
    qp.x = __shfl_xor_sync(0xffffffffu, q.x, 4);
    qp.y = __shfl_xor_sync(0xffffffffu, q.y, 4);
    qp.z = __shfl_xor_sync(0xffffffffu, q.z, 4);
    qp.w = __shfl_xor_sync(0xffffffffu, q.w, 4);
    kp.x = __shfl_xor_sync(0xffffffffu, k.x, 4);
    kp.y = __shfl_xor_sync(0xffffffffu, k.y, 4);
    kp.z = __shfl_xor_sync(0xffffffffu, k.z, 4);
    kp.w = __shfl_xor_sync(0xffffffffu, k.w, 4);

    if (lane < 8) {
        const float sgn = (lane < 4) ? -1.0f : 1.0f;
        float qa[4] = {q.x, q.y, q.z, q.w};
        float pa[4] = {qp.x, qp.y, qp.z, qp.w};
        float ka[4] = {k.x, k.y, k.z, k.w};
        float kb[4] = {kp.x, kp.y, kp.z, kp.w};
#pragma unroll
        for (int i = 0; i < 4; i++) {
            int j = (lane & 3) * 4 + i;
            float inv = __expf(-(float)(2 * j) * (9.210340371976184f / 32.0f));
            float sn, cs;
            sincosf((float)s * inv, &sn, &cs);
            qa[i] = qa[i] * cs + sgn * pa[i] * sn;
            ka[i] = ka[i] * cs + sgn * kb[i] * sn;
        }
        q = make_float4(qa[0], qa[1], qa[2], qa[3]);
        k = make_float4(ka[0], ka[1], ka[2], ka[3]);
    }

    const size_t o = (size_t)(b * SS + s) * HH + h * HDIM + d0;
    __nv_bfloat16 h0, h1, h2, h3, l0, l1, l2, l3;
    split1(q.x, h0, l0); split1(q.y, h1, l1);
    split1(q.z, h2, l2); split1(q.w, h3, l3);
    *(uint2*)(g_qh + o) = make_uint2(pack2(h0, h1), pack2(h2, h3));
    *(uint2*)(g_ql + o) = make_uint2(pack2(l0, l1), pack2(l2, l3));
    split1(k.x, h0, l0); split1(k.y, h1, l1);
    split1(k.z, h2, l2); split1(k.w, h3, l3);
    *(uint2*)(g_kh + o) = make_uint2(pack2(h0, h1), pack2(h2, h3));
    *(uint2*)(g_kl + o) = make_uint2(pack2(l0, l1), pack2(l2, l3));
}

// ============================================================================
// WMMA split-bf16 GEMM: 128(M) x BN(N) CTA tile, 512 threads = 16 warps,
// warp grid 2(M) x 8(N), warp tile 64 x WN (WN = BN/8), K-chunk 32,
// 2-stage cp.async pipeline. WN=32 -> BN=256 (big); WN=16 -> BN=128 (small).
// Output: fp32 C (Chi==null) or bf16 hi/lo (Chi/Clo set).
// ============================================================================
#define PADE    40                        // smem row stride in bf16 elems
#define A_TILE  (128 * PADE * 2)          // 10240 B

template <int WN>
__global__ __launch_bounds__(512, 1) void gemm_wmma_kernel(
    const __nv_bfloat16* __restrict__ Ah, const __nv_bfloat16* __restrict__ Al,
    const __nv_bfloat16* __restrict__ Bh, const __nv_bfloat16* __restrict__ Bl,
    const float* __restrict__ bias,
    float* __restrict__ C,
    __nv_bfloat16* __restrict__ Chi, __nv_bfloat16* __restrict__ Clo,
    int ldc, int N, int K)
{
    constexpr int BN      = WN * 8;
    constexpr int B_TILE  = BN * PADE * 2;
    constexpr int STAGE   = 2 * A_TILE + 2 * B_TILE;
    constexpr int NJ      = WN / 16;

    extern __shared__ char smem[];
    const uint32_t sbase = smem_u32(smem);
    const int t    = threadIdx.x;
    const int w    = t >> 5;
    const int lane = t & 31;
    const int wm   = w >> 3;     // 0..1
    const int wn   = w & 7;      // 0..7
    const int m0   = blockIdx.y * 128;
    const int n0   = blockIdx.x * BN;

    wmma::fragment<wmma::accumulator, 16, 16, 16, float> acc[4][NJ];
#pragma unroll
    for (int i = 0; i < 4; i++)
#pragma unroll
        for (int j = 0; j < NJ; j++) wmma::fill_fragment(acc[i][j], 0.0f);

    const int nchunks = K / 32;

    auto load_stage = [&](int chunk, int stage) {
        const int kk = chunk * 32;
        const uint32_t sst = sbase + stage * STAGE;
        // A tiles: 1024 cp16 over 512 threads
#pragma unroll
        for (int rep = 0; rep < 2; rep++) {
            const int v = t + rep * 512;
            const int tile = v >> 9;
            const int r = (v >> 2) & 127;
            const int c = (v & 3) * 8;
            const __nv_bfloat16* src = tile ? Al : Ah;
            cp16(sst + tile * A_TILE + r * (PADE * 2) + c * 2,
                 src + (size_t)(m0 + r) * K + kk + c, 16);
        }
        // B tiles: BN*8 cp16
        constexpr int BREP = (BN * 8) / 512;
#pragma unroll
        for (int rep = 0; rep < BREP; rep++) {
            const int v = t + rep * 512;
            const int tile = v / (BN * 4);
            const int r = (v >> 2) % BN;
            const int c = (v & 3) * 8;
            const __nv_bfloat16* src = tile ? Bl : Bh;
            const int brow = n0 + r;
            const uint32_t vb = (brow < N) ? 16u : 0u;
            cp16(sst + 2 * A_TILE + tile * B_TILE + r * (PADE * 2) + c * 2,
                 src + (size_t)(brow < N ? brow : 0) * K + kk + c, vb);
        }
        cp_commit();
    };

    load_stage(0, 0);

    for (int chunk = 0; chunk < nchunks; chunk++) {
        const int stage = chunk & 1;
        if (chunk + 1 < nchunks) { load_stage(chunk + 1, stage ^ 1); cp_wait<1>(); }
        else cp_wait<0>();
        __syncthreads();

        const __nv_bfloat16* sAh = (const __nv_bfloat16*)(smem + stage * STAGE);
        const __nv_bfloat16* sAl = (const __nv_bfloat16*)(smem + stage * STAGE + A_TILE);
        const __nv_bfloat16* sBh = (const __nv_bfloat16*)(smem + stage * STAGE + 2 * A_TILE);
        const __nv_bfloat16* sBl = (const __nv_bfloat16*)(smem + stage * STAGE + 2 * A_TILE + B_TILE);

#pragma unroll
        for (int ks = 0; ks < 2; ks++) {
            // B fragments for this warp's WN columns (kept live: NJ*2 frags)
            wmma::fragment<wmma::matrix_b, 16, 16, 16, __nv_bfloat16, wmma::col_major> bh[NJ], bl[NJ];
#pragma unroll
            for (int j = 0; j < NJ; j++) {
                const int col = wn * WN + j * 16;
                wmma::load_matrix_sync(bh[j], sBh + col * PADE + ks * 16, PADE);
                wmma::load_matrix_sync(bl[j], sBl + col * PADE + ks * 16, PADE);
            }
            // A fragments loaded per-i (reg-lean)
#pragma unroll
            for (int i = 0; i < 4; i++) {
                const int row = wm * 64 + i * 16;
                wmma::fragment<wmma::matrix_a, 16, 16, 16, __nv_bfloat16, wmma::row_major> ah, al;
                wmma::load_matrix_sync(ah, sAh + row * PADE + ks * 16, PADE);
                wmma::load_matrix_sync(al, sAl + row * PADE + ks * 16, PADE);
#pragma unroll
                for (int j = 0; j < NJ; j++) {
                    wmma::mma_sync(acc[i][j], ah, bh[j], acc[i][j]);
                    wmma::mma_sync(acc[i][j], ah, bl[j], acc[i][j]);
                    wmma::mma_sync(acc[i][j], al, bh[j], acc[i][j]);
                }
            }
        }
        __syncthreads();
    }

    // epilogue: per-warp 16x16 staging in smem
    float* epi = (float*)(smem) + w * 256;
#pragma unroll
    for (int i = 0; i < 4; i++)
#pragma unroll
        for (int j = 0; j < NJ; j++) {
            const int gcol0 = n0 + wn * WN + j * 16;
            if (gcol0 < N) {
                wmma::store_matrix_sync(epi, acc[i][j], 16, wmma::mem_row_major);
                __syncwarp();
                const int row  = lane >> 1;
                const int coff = (lane & 1) * 8;
                const int grow = m0 + wm * 64 + i * 16 + row;
                const int gcol = gcol0 + coff;
                float4 b0 = *(const float4*)(bias + gcol);
                float4 b1 = *(const float4*)(bias + gcol + 4);
                const float* e = epi + row * 16 + coff;
                float vals[8] = {e[0] + b0.x, e[1] + b0.y, e[2] + b0.z, e[3] + b0.w,
                                 e[4] + b1.x, e[5] + b1.y, e[6] + b1.z, e[7] + b1.w};
                if (Chi == nullptr) {
                    float* cp = C + (size_t)grow * ldc + gcol;
                    *(float4*)cp       = make_float4(vals[0], vals[1], vals[2], vals[3]);
                    *(float4*)(cp + 4) = make_float4(vals[4], vals[5], vals[6], vals[7]);
                } else {
                    __nv_bfloat16 hh[8], ll[8];
#pragma unroll
                    for (int c = 0; c < 8; c++) split1(vals[c], hh[c], ll[c]);
                    uint4 uh = make_uint4(pack2(hh[0], hh[1]), pack2(hh[2], hh[3]),
                                          pack2(hh[4], hh[5]), pack2(hh[6], hh[7]));
                    uint4 ul = make_uint4(pack2(ll[0], ll[1]), pack2(ll[2], ll[3]),
                                          pack2(ll[4], ll[5]), pack2(ll[6], ll[7]));
                    *(uint4*)(Chi + (size_t)grow * ldc + gcol) = uh;
                    *(uint4*)(Clo + (size_t)grow * ldc + gcol) = ul;
                }
                __syncwarp();
            }
        }
}

#define GEMM_SMEM_BIG   (2 * (2 * A_TILE + 2 * (256 * PADE * 2)))   // 122880
#define GEMM_SMEM_SMALL (2 * (2 * A_TILE + 2 * (128 * PADE * 2)))   // 81920

// ============================================================================
// WMMA flash attention (causal) — unchanged from R7
// ============================================================================
#define FQ_LD 136
#define FS_LD 68
#define FP_LD 72
#define FO_LD 132
#define QH_OFF 0
#define QL_OFF 17408
#define KH_OFF 34816
#define KL_OFF 52224
#define VH_OFF 69632
#define VL_OFF 87040
#define S_OFF  104448
#define PH_OFF 121856
#define PL_OFF 131072
#define OT_OFF 140288
#define FLASH_SMEM 174080

__global__ __launch_bounds__(256, 1) void flash_kernel()
{
    extern __shared__ char sm[];
    const uint32_t sb = smem_u32(sm);
    __nv_bfloat16* Qh = (__nv_bfloat16*)(sm + QH_OFF);
    __nv_bfloat16* Ql = (__nv_bfloat16*)(sm + QL_OFF);
    __nv_bfloat16* Kh = (__nv_bfloat16*)(sm + KH_OFF);
    __nv_bfloat16* Kl = (__nv_bfloat16*)(sm + KL_OFF);
    __nv_bfloat16* Vh = (__nv_bfloat16*)(sm + VH_OFF);
    __nv_bfloat16* Vl = (__nv_bfloat16*)(sm + VL_OFF);
    float*         Ss = (float*)(sm + S_OFF);
    __nv_bfloat16* Ph = (__nv_bfloat16*)(sm + PH_OFF);
    __nv_bfloat16* Pl = (__nv_bfloat16*)(sm + PL_OFF);
    float*         Ot = (float*)(sm + OT_OFF);

    const int qt = blockIdx.x;
    const int h  = blockIdx.y;
    const int b  = blockIdx.z;
    const int q0 = qt * 64;
    const int t  = threadIdx.x;
    const int tx = t & 15;
    const int ty = t >> 4;
    const int w  = t >> 5;
    const int wr = w >> 1;
    const int wc = w & 1;

    for (int i = t; i < 1024; i += 256) {
        const int r = i >> 4;
        const int c = (i & 15) << 3;
        const size_t g = (size_t)(b * SS + q0 + r) * HH + h * HDIM + c;
        const uint32_t so = (uint32_t)((r * FQ_LD + c) * 2);
        cp16(sb + QH_OFF + so, g_qh + g, 16);
        cp16(sb + QL_OFF + so, g_ql + g, 16);
    }
    cp_commit();

    float m_i[4], l_i[4], O[4][8];
#pragma unroll
    for (int i = 0; i < 4; i++) {
        m_i[i] = -1e30f; l_i[i] = 0.0f;
#pragma unroll
        for (int c = 0; c < 8; c++) O[i][c] = 0.0f;
    }
    const float scale = 0.08838834764831843f;

    for (int kt = 0; kt <= qt; kt++) {
        const int k0 = kt * 64;
        for (int i = t; i < 1024; i += 256) {
            const int r = i >> 4;
            const int c = (i & 15) << 3;
            const size_t g = (size_t)(b * SS + k0 + r) * HH + h * HDIM + c;
            const uint32_t so = (uint32_t)((r * FQ_LD + c) * 2);
            cp16(sb + KH_OFF + so, g_kh + g, 16);
            cp16(sb + KL_OFF + so, g_kl + g, 16);
        }
        cp_commit();
        for (int i = t; i < 1024; i += 256) {
            const int r = i >> 4;
            const int c = (i & 15) << 3;
            const size_t g = (size_t)(b * SS + k0 + r) * HH + h * HDIM + c;
            const uint32_t so = (uint32_t)((r * FQ_LD + c) * 2);
            cp16(sb + VH_OFF + so, g_vrh + g, 16);
            cp16(sb + VL_OFF + so, g_vrl + g, 16);
        }
        cp_commit();
        cp_wait<1>();
        __syncthreads();

        {
            wmma::fragment<wmma::accumulator, 16, 16, 16, float> sacc[2];
            wmma::fill_fragment(sacc[0], 0.0f);
            wmma::fill_fragment(sacc[1], 0.0f);
#pragma unroll
            for (int k = 0; k < 8; k++) {
                wmma::fragment<wmma::matrix_a, 16, 16, 16, __nv_bfloat16, wmma::row_major> ah, al;
                wmma::load_matrix_sync(ah, Qh + (wr * 16) * FQ_LD + k * 16, FQ_LD);
                wmma::load_matrix_sync(al, Ql + (wr * 16) * FQ_LD + k * 16, FQ_LD);
#pragma unroll
                for (int jj = 0; jj < 2; jj++) {
                    const int col0 = wc * 32 + jj * 16;
                    wmma::fragment<wmma::matrix_b, 16, 16, 16, __nv_bfloat16, wmma::col_major> bh, bl;
                    wmma::load_matrix_sync(bh, Kh + col0 * FQ_LD + k * 16, FQ_LD);
                    wmma::load_matrix_sync(bl, Kl + col0 * FQ_LD + k * 16, FQ_LD);
                    wmma::mma_sync(sacc[jj], ah, bh, sacc[jj]);
                    wmma::mma_sync(sacc[jj], al, bh, sacc[jj]);
                    wmma::mma_sync(sacc[jj], ah, bl, sacc[jj]);
                }
            }
#pragma unroll
            for (int jj = 0; jj < 2; jj++)
                wmma::store_matrix_sync(&Ss[(wr * 16) * FS_LD + wc * 32 + jj * 16],
                                        sacc[jj], FS_LD, wmma::mem_row_major);
        }
        __syncthreads();

        float corr[4];
#pragma unroll
        for (int i = 0; i < 4; i++) {
            const int row = ty * 4 + i;
            const int qg  = q0 + row;
            float sv[4], rmax = -1e30f;
#pragma unroll
            for (int j = 0; j < 4; j++) {
                float s = Ss[row * FS_LD + tx + 16 * j] * scale;
                if (k0 + tx + 16 * j > qg) s = -1e30f;
                sv[j] = s;
                rmax = fmaxf(rmax, s);
            }
#pragma unroll
            for (int off = 8; off >= 1; off >>= 1)
                rmax = fmaxf(rmax, __shfl_xor_sync(0xffffffffu, rmax, off));
            const float mnew = fmaxf(m_i[i], rmax);
            corr[i] = __expf(m_i[i] - mnew);
            float rsum = 0.0f;
#pragma unroll
            for (int j = 0; j < 4; j++) {
                const float p = __expf(sv[j] - mnew);
                __nv_bfloat16 ph, pl;
                split1(p, ph, pl);
                Ph[row * FP_LD + tx + 16 * j] = ph;
                Pl[row * FP_LD + tx + 16 * j] = pl;
                rsum += p;
            }
#pragma unroll
            for (int off = 8; off >= 1; off >>= 1)
                rsum += __shfl_xor_sync(0xffffffffu, rsum, off);
            l_i[i] = l_i[i] * corr[i] + rsum;
            m_i[i] = mnew;
        }
        cp_wait<0>();
        __syncthreads();

        {
            wmma::fragment<wmma::accumulator, 16, 16, 16, float> oacc[4];
#pragma unroll
            for (int jj = 0; jj < 4; jj++) wmma::fill_fragment(oacc[jj], 0.0f);
#pragma unroll
            for (int k = 0; k < 4; k++) {
                wmma::fragment<wmma::matrix_a, 16, 16, 16, __nv_bfloat16, wmma::row_major> pah, pal;
                wmma::load_matrix_sync(pah, Ph + (wr * 16) * FP_LD + k * 16, FP_LD);
                wmma::load_matrix_sync(pal, Pl + (wr * 16) * FP_LD + k * 16, FP_LD);
#pragma unroll
                for (int jj = 0; jj < 4; jj++) {
                    const int col0 = wc * 64 + jj * 16;
                    wmma::fragment<wmma::matrix_b, 16, 16, 16, __nv_bfloat16, wmma::row_major> vbh, vbl;
                    wmma::load_matrix_sync(vbh, Vh + (k * 16) * FQ_LD + col0, FQ_LD);
                    wmma::load_matrix_sync(vbl, Vl + (k * 16) * FQ_LD + col0, FQ_LD);
                    wmma::mma_sync(oacc[jj], pah, vbh, oacc[jj]);
                    wmma::mma_sync(oacc[jj], pal, vbh, oacc[jj]);
                    wmma::mma_sync(oacc[jj], pah, vbl, oacc[jj]);
                }
            }
#pragma unroll
            for (int jj = 0; jj < 4; jj++)
                wmma::store_matrix_sync(&Ot[(wr * 16) * FO_LD + wc * 64 + jj * 16],
                                        oacc[jj], FO_LD, wmma::mem_row_major);
        }
        __syncthreads();

#pragma unroll
        for (int i = 0; i < 4; i++) {
            const int row = ty * 4 + i;
#pragma unroll
            for (int c = 0; c < 8; c++)
                O[i][c] = O[i][c] * corr[i] + Ot[row * FO_LD + tx * 8 + c];
        }
    }

#pragma unroll
    for (int i = 0; i < 4; i++) {
        const float inv = 1.0f / l_i[i];
        const int qg = q0 + ty * 4 + i;
        const size_t o = (size_t)(b * SS + qg) * HH + h * HDIM + tx * 8;
        __nv_bfloat16 hh[8], ll[8];
#pragma unroll
        for (int c = 0; c < 8; c++) split1(O[i][c] * inv, hh[c], ll[c]);
        *(uint4*)(g_ath + o) = make_uint4(pack2(hh[0], hh[1]), pack2(hh[2], hh[3]),
                                          pack2(hh[4], hh[5]), pack2(hh[6], hh[7]));
        *(uint4*)(g_atl + o) = make_uint4(pack2(ll[0], ll[1]), pack2(ll[2], ll[3]),
                                          pack2(ll[4], ll[5]), pack2(ll[6], ll[7]));
    }
}

// ============================================================================
// Launch
// ============================================================================
static inline void split_launch(const float* s, __nv_bfloat16* h, __nv_bfloat16* l, int n)
{
    split_kernel<<<(n / 4 + 255) / 256, 256>>>(s, h, l, n);
}

extern "C" void kernel_launch(void* const* d_in, const int* in_sizes, int n_in,
                              void* d_out, int out_size)
{
    const float* x    = (const float*)d_in[0];
    const float* Wqkv = (const float*)d_in[1];
    const float* bqkv = (const float*)d_in[2];
    const float* Wc   = (const float*)d_in[3];
    const float* bc   = (const float*)d_in[4];
    const float* Wr   = (const float*)d_in[5];
    const float* br   = (const float*)d_in[6];
    const float* Wd   = (const float*)d_in[7];
    const float* bd   = (const float*)d_in[8];
    float* out = (float*)d_out;

    float* qkv;
    cudaGetSymbolAddress((void**)&qkv, g_qkv);
    __nv_bfloat16 *xh, *xl, *wqh, *wql, *vh, *vl, *wch, *wcl,
                  *vch, *vcl, *wrh, *wrl, *ath, *atl, *wdh, *wdl, *vrh, *vrl;
    cudaGetSymbolAddress((void**)&xh,  g_xh);  cudaGetSymbolAddress((void**)&xl,  g_xl);
    cudaGetSymbolAddress((void**)&wqh, g_wqh); cudaGetSymbolAddress((void**)&wql, g_wql);
    cudaGetSymbolAddress((void**)&vh,  g_vh);  cudaGetSymbolAddress((void**)&vl,  g_vl);
    cudaGetSymbolAddress((void**)&wch, g_wch); cudaGetSymbolAddress((void**)&wcl, g_wcl);
    cudaGetSymbolAddress((void**)&vch, g_vch); cudaGetSymbolAddress((void**)&vcl, g_vcl);
    cudaGetSymbolAddress((void**)&wrh, g_wrh); cudaGetSymbolAddress((void**)&wrl, g_wrl);
    cudaGetSymbolAddress((void**)&ath, g_ath); cudaGetSymbolAddress((void**)&atl, g_atl);
    cudaGetSymbolAddress((void**)&wdh, g_wdh); cudaGetSymbolAddress((void**)&wdl, g_wdl);
    cudaGetSymbolAddress((void**)&vrh, g_vrh); cudaGetSymbolAddress((void**)&vrl, g_vrl);

    cudaFuncSetAttribute(gemm_wmma_kernel<32>,
                         cudaFuncAttributeMaxDynamicSharedMemorySize, GEMM_SMEM_BIG);
    cudaFuncSetAttribute(gemm_wmma_kernel<16>,
                         cudaFuncAttributeMaxDynamicSharedMemorySize, GEMM_SMEM_SMALL);
    cudaFuncSetAttribute(flash_kernel,
                         cudaFuncAttributeMaxDynamicSharedMemorySize, FLASH_SMEM);

    // 1. qkv = x @ Wqkv^T + bqkv  (fp32 out; feeds rope + v split)
    split_launch(x, xh, xl, MALL * HH);
    split_launch(Wqkv, wqh, wql, H3 * HH);
    gemm_wmma_kernel<32><<<dim3(H3 / 256, MALL / 128), 512, GEMM_SMEM_BIG>>>(
        xh, xl, wqh, wql, bqkv, qkv, nullptr, nullptr, H3, H3, HH);

    // 2. fused RoPE + q/k split
    rope_split_kernel<<<BB * SS * NHEAD / 8, 256>>>();

    // 3. vc = v @ Wc^T + bc  -> bf16 hi/lo directly (small tile: 96 CTAs)
    split_v_kernel<<<(MALL * HH / 4 + 255) / 256, 256>>>();
    split_launch(Wc, wch, wcl, VP * HH);
    gemm_wmma_kernel<16><<<dim3((VP + 127) / 128, MALL / 128), 512, GEMM_SMEM_SMALL>>>(
        vh, vl, wch, wcl, bc, nullptr, vch, vcl, VP, VP, HH);

    // 4. vr = vc @ Wr^T + br -> bf16 hi/lo directly
    split_launch(Wr, wrh, wrl, HH * VP);
    gemm_wmma_kernel<32><<<dim3(HH / 256, MALL / 128), 512, GEMM_SMEM_BIG>>>(
        vch, vcl, wrh, wrl, br, nullptr, vrh, vrl, HH, HH, VP);

    // 5. flash attention -> ath/atl
    flash_kernel<<<dim3(SS / 64, NHEAD, BB), 256, FLASH_SMEM>>>();

    // 6. out = att @ Wd^T + bd (fp32)
    split_launch(Wd, wdh, wdl, HH * HH);
    gemm_wmma_kernel<32><<<dim3(HH / 256, MALL / 128), 512, GEMM_SMEM_BIG>>>(
        ath, atl, wdh, wdl, bd, out, nullptr, nullptr, HH, HH, HH);
}